// round 10
// baseline (speedup 1.0000x reference)
#include <cuda_runtime.h>
#include <cuda_fp16.h>
#include <math.h>
#include <stdint.h>

// ---------------- scratch (allocation-free: __device__ globals) ----------------
__device__ __align__(1024) uint32_t g_xs_big[32768ULL * 64];
__device__ __align__(1024) uint32_t g_xs_sml[32768ULL * 64];
__device__ __align__(1024) uint32_t g_h_big[32768ULL * 256];
__device__ __align__(1024) uint32_t g_h_sml[32768ULL * 256];
__device__ __align__(1024) float    g_params[32768ULL * 1792];
__device__ __align__(1024) uint32_t g_w0b[2][512 * 64];
__device__ __align__(1024) uint32_t g_w0s[2][512 * 64];
__device__ __align__(1024) uint32_t g_w1b[2][1792 * 256];
__device__ __align__(1024) uint32_t g_w1s[2][1792 * 256];

#define BVAL   3.0f
#define KBINS  5
#define MIN_BW 0.001f
#define MIN_BH 0.001f
#define MIN_DV 0.001f

// ======================= helpers =======================
__device__ __forceinline__ int gidx(int kpg) {
    return (kpg & ~15) | ((kpg & 3) << 2) | ((kpg >> 2) & 3);
}

__device__ __forceinline__ void split2h(float x0, float x1, uint32_t& b, uint32_t& s) {
    __half b0 = __float2half_rn(x0);
    __half b1 = __float2half_rn(x1);
    float r0 = x0 - __half2float(b0);
    float r1 = x1 - __half2float(b1);
    __half s0 = __float2half_rn(r0);
    __half s1 = __float2half_rn(r1);
    b = (uint32_t)__half_as_ushort(b0) | ((uint32_t)__half_as_ushort(b1) << 16);
    s = (uint32_t)__half_as_ushort(s0) | ((uint32_t)__half_as_ushort(s1) << 16);
}

__device__ __forceinline__ void mma_h(float* d,
                                      uint32_t a0, uint32_t a1, uint32_t a2, uint32_t a3,
                                      uint32_t b0, uint32_t b1) {
    asm volatile(
        "mma.sync.aligned.m16n8k16.row.col.f32.f16.f16.f32 "
        "{%0,%1,%2,%3}, {%4,%5,%6,%7}, {%8,%9}, {%0,%1,%2,%3};"
        : "+f"(d[0]), "+f"(d[1]), "+f"(d[2]), "+f"(d[3])
        : "r"(a0), "r"(a1), "r"(a2), "r"(a3), "r"(b0), "r"(b1));
}

#define CP16(dst, src) \
    asm volatile("cp.async.cg.shared.global [%0], [%1], 16;" :: "r"(dst), "l"(src) : "memory")
#define CP_COMMIT() asm volatile("cp.async.commit_group;" ::: "memory")
#define CP_WAIT1()  asm volatile("cp.async.wait_group 1;" ::: "memory")
#define CP_WAIT0()  asm volatile("cp.async.wait_group 0;" ::: "memory")

__device__ __forceinline__ uint32_t smem_u32(const void* p) {
    uint32_t a;
    asm("{ .reg .u64 t; cvta.to.shared.u64 t, %1; cvt.u32.u64 %0, t; }" : "=r"(a) : "l"(p));
    return a;
}

// ======================= converters =======================
__device__ __forceinline__ void conv_w_body(
    const float* __restrict__ w, int M, int K2, int m0, int kp0,
    uint32_t* __restrict__ ob, uint32_t* __restrict__ os,
    uint32_t (*tb)[33], uint32_t (*ts)[33], int tid)
{
    const int xx = tid & 31, yy = tid >> 5;
    for (int i = yy; i < 32; i += 8) {
        int kpg = kp0 + i, m = m0 + xx;
        float v0 = w[(size_t)(2 * kpg) * M + m];
        float v1 = w[(size_t)(2 * kpg + 1) * M + m];
        split2h(v0, v1, tb[i][xx], ts[i][xx]);
    }
    __syncthreads();
    for (int i = yy; i < 32; i += 8) {
        int m = m0 + i;
        size_t dst = (size_t)m * K2 + gidx(kp0 + xx);
        ob[dst] = tb[xx][i]; os[dst] = ts[xx][i];
    }
}

__global__ void __launch_bounds__(256) conv_all(
    const float* __restrict__ x, int xoff,
    const float* __restrict__ w0, const float* __restrict__ w1,
    uint32_t* __restrict__ w0bD, uint32_t* __restrict__ w0sD,
    uint32_t* __restrict__ w1bD, uint32_t* __restrict__ w1sD,
    uint32_t* __restrict__ xb, uint32_t* __restrict__ xs)
{
    __shared__ uint32_t tb[32][33], ts[32][33];
    const int bid = blockIdx.x;
    const int tid = threadIdx.x;
    if (bid < 32) {
        conv_w_body(w0, 512, 64, (bid & 15) * 32, (bid >> 4) * 32, w0bD, w0sD, tb, ts, tid);
    } else if (bid < 480) {
        int b = bid - 32;
        conv_w_body(w1, 1792, 256, (b % 56) * 32, (b / 56) * 32, w1bD, w1sD, tb, ts, tid);
    } else {
        int t = (bid - 480) * 256 + tid;
        int row = t >> 6, kpg = t & 63;
        float2 v = *(const float2*)(x + (size_t)row * 256 + xoff + 2 * kpg);
        uint32_t b_, s_;
        split2h(v.x, v.y, b_, s_);
        int dst = row * 64 + gidx(kpg);
        xb[dst] = b_; xs[dst] = s_;
    }
}

__global__ void __launch_bounds__(256) conv_x(const float* __restrict__ x, int xoff,
                                              uint32_t* __restrict__ ob,
                                              uint32_t* __restrict__ os) {
    int t = blockIdx.x * 256 + threadIdx.x;
    int row = t >> 6, kpg = t & 63;
    float2 v = *(const float2*)(x + (size_t)row * 256 + xoff + 2 * kpg);
    uint32_t b, s;
    split2h(v.x, v.y, b, s);
    int dst = row * 64 + gidx(kpg);
    ob[dst] = b; os[dst] = s;
}

// ======================= fp16x3 tensor-core GEMM (64x64 warp tiles) =======================
// Block tile 128x128, 128 threads = 4 warps (2m x 2n), warp tile 64x64.
// BK = 16 words (32 k). 3-stage cp.async pipeline; stage 32KB: Ab|As|Bb|Bs @ 8KB.
// 3 f32-acc terms: Ab*Bb + As*Bb + Ab*Bs.
#define GEMM_SMEM (3 * 32768)

template <int EPI>
__global__ void __launch_bounds__(128, 2) gemm_h3(
    const uint32_t* __restrict__ Ab, const uint32_t* __restrict__ As,
    const uint32_t* __restrict__ Bb, const uint32_t* __restrict__ Bs,
    const float* __restrict__ bias,
    float* __restrict__ C, uint32_t* __restrict__ Hb, uint32_t* __restrict__ Hs,
    int M, int K2)
{
    extern __shared__ uint32_t sm[];
    const uint32_t sbase = smem_u32(sm);
    const int tid  = threadIdx.x;
    const int lane = tid & 31;
    const int wid  = tid >> 5;        // 0..3
    const int warp_m = wid & 1;       // 64-row half
    const int warp_n = wid >> 1;      // 64-col half
    const int rowBase = blockIdx.y * 128;
    const int colBase = blockIdx.x * 128;
    const int q  = lane & 3;
    const int rw = lane >> 2;

    // staging: thread -> row tid (0..127), 4 x CP16 per array (64B/row)
    const uint32_t* gAb = Ab + (size_t)(rowBase + tid) * K2;
    const uint32_t* gAs = As + (size_t)(rowBase + tid) * K2;
    const uint32_t* gBb = Bb + (size_t)(colBase + tid) * K2;
    const uint32_t* gBs = Bs + (size_t)(colBase + tid) * K2;
    const uint32_t sdst = sbase + (uint32_t)tid * 64u;

#define STAGE(it, buf) do { \
        uint32_t d0 = sdst + (uint32_t)(buf) * 32768u; \
        const uint32_t* pa = gAb + (it) * 16; \
        const uint32_t* ps = gAs + (it) * 16; \
        const uint32_t* pb = gBb + (it) * 16; \
        const uint32_t* pq = gBs + (it) * 16; \
        CP16(d0,          pa);     CP16(d0 + 16,         pa + 4); \
        CP16(d0 + 32,     pa + 8); CP16(d0 + 48,         pa + 12); \
        CP16(d0 + 8192,       ps);     CP16(d0 + 8192 + 16,  ps + 4); \
        CP16(d0 + 8192 + 32,  ps + 8); CP16(d0 + 8192 + 48,  ps + 12); \
        CP16(d0 + 16384,      pb);     CP16(d0 + 16384 + 16, pb + 4); \
        CP16(d0 + 16384 + 32, pb + 8); CP16(d0 + 16384 + 48, pb + 12); \
        CP16(d0 + 24576,      pq);     CP16(d0 + 24576 + 16, pq + 4); \
        CP16(d0 + 24576 + 32, pq + 8); CP16(d0 + 24576 + 48, pq + 12); \
        CP_COMMIT(); \
    } while (0)

    float acc[4][8][4];
#pragma unroll
    for (int mt = 0; mt < 4; mt++)
#pragma unroll
        for (int nt = 0; nt < 8; nt++)
#pragma unroll
            for (int c = 0; c < 4; c++) acc[mt][nt][c] = 0.f;

    const int nIter = K2 >> 4;
    STAGE(0, 0);
    STAGE(1, 1);

    int buf = 0;
    for (int it = 0; it < nIter; it++) {
        if (it + 1 < nIter) { CP_WAIT1(); } else { CP_WAIT0(); }
        __syncthreads();
        if (it + 2 < nIter) {
            int nb = buf + 2; if (nb >= 3) nb -= 3;
            STAGE(it + 2, nb);
        }
        const uint32_t* sA = sm + buf * 8192;
        const uint32_t* sB = sA + 4096;

        uint4 bb[8], bs[8];
#pragma unroll
        for (int nt = 0; nt < 8; nt++) {
            const uint32_t* p = sB + (warp_n * 64 + nt * 8 + rw) * 16 + 4 * q;
            bb[nt] = *(const uint4*)p;
            bs[nt] = *(const uint4*)(p + 2048);
        }
#pragma unroll
        for (int mt = 0; mt < 4; mt++) {
            const uint32_t* p = sA + (warp_m * 64 + mt * 16 + rw) * 16 + 4 * q;
            uint4 alo = *(const uint4*)p;
            uint4 ahi = *(const uint4*)(p + 128);
            uint4 slo = *(const uint4*)(p + 2048);
            uint4 shi = *(const uint4*)(p + 2048 + 128);
            // term 1: Ab*Bb (ks0, ks1)
#pragma unroll
            for (int nt = 0; nt < 8; nt++)
                mma_h(acc[mt][nt], alo.x, ahi.x, alo.y, ahi.y, bb[nt].x, bb[nt].y);
#pragma unroll
            for (int nt = 0; nt < 8; nt++)
                mma_h(acc[mt][nt], alo.z, ahi.z, alo.w, ahi.w, bb[nt].z, bb[nt].w);
            // term 2: As*Bb
#pragma unroll
            for (int nt = 0; nt < 8; nt++)
                mma_h(acc[mt][nt], slo.x, shi.x, slo.y, shi.y, bb[nt].x, bb[nt].y);
#pragma unroll
            for (int nt = 0; nt < 8; nt++)
                mma_h(acc[mt][nt], slo.z, shi.z, slo.w, shi.w, bb[nt].z, bb[nt].w);
            // term 3: Ab*Bs
#pragma unroll
            for (int nt = 0; nt < 8; nt++)
                mma_h(acc[mt][nt], alo.x, ahi.x, alo.y, ahi.y, bs[nt].x, bs[nt].y);
#pragma unroll
            for (int nt = 0; nt < 8; nt++)
                mma_h(acc[mt][nt], alo.z, ahi.z, alo.w, ahi.w, bs[nt].z, bs[nt].w);
        }
        buf++; if (buf >= 3) buf -= 3;
    }

    // ---- epilogue ----
#pragma unroll
    for (int mt = 0; mt < 4; mt++) {
#pragma unroll
        for (int nt = 0; nt < 8; nt++) {
            int row = rowBase + warp_m * 64 + mt * 16 + rw;
            int col = colBase + warp_n * 64 + nt * 8 + q * 2;
            float b0 = bias[col], b1 = bias[col + 1];
            float v0 = acc[mt][nt][0] + b0, v1 = acc[mt][nt][1] + b1;
            float v2 = acc[mt][nt][2] + b0, v3 = acc[mt][nt][3] + b1;
            if (EPI == 1) {
                v0 = tanhf(v0); v1 = tanhf(v1); v2 = tanhf(v2); v3 = tanhf(v3);
                int dcol = gidx(col >> 1);
                uint32_t bbv, ssv;
                split2h(v0, v1, bbv, ssv);
                Hb[(size_t)row * (M >> 1) + dcol] = bbv;
                Hs[(size_t)row * (M >> 1) + dcol] = ssv;
                split2h(v2, v3, bbv, ssv);
                Hb[(size_t)(row + 8) * (M >> 1) + dcol] = bbv;
                Hs[(size_t)(row + 8) * (M >> 1) + dcol] = ssv;
            } else {
                *(float2*)&C[(size_t)row * M + col]       = make_float2(v0, v1);
                *(float2*)&C[(size_t)(row + 8) * M + col] = make_float2(v2, v3);
            }
        }
    }
#undef STAGE
}

// ======================= spline =======================
__device__ __forceinline__ float softplusf(float x) {
    return (x > 20.0f) ? x : log1pf(expf(x));
}

__global__ void __launch_bounds__(128) spline_kernel(
    const float* __restrict__ xin, int xoff,
    const float* __restrict__ params,
    float* __restrict__ z, int zoff,
    float* __restrict__ logdet, int add)
{
    const int n = blockIdx.x;
    const int d = threadIdx.x;

    __shared__ float ps[1792];
    {
        const float4* src = (const float4*)(params + (size_t)n * 1792);
#pragma unroll
        for (int i = 0; i < 3; i++)
            *(float4*)&ps[(d + i * 128) * 4] = src[d + i * 128];
        if (d < 64) *(float4*)&ps[(d + 384) * 4] = src[d + 384];
    }
    __syncthreads();

    float raw[14];
#pragma unroll
    for (int j = 0; j < 14; j++) raw[j] = ps[d * 14 + j];

    const float t = xin[(size_t)n * 256 + xoff + d];

    float cw[6], wd[5];
    {
        float m = raw[0];
#pragma unroll
        for (int j = 1; j < 5; j++) m = fmaxf(m, raw[j]);
        float e[5], s = 0.f;
#pragma unroll
        for (int j = 0; j < 5; j++) { e[j] = expf(raw[j] - m); s += e[j]; }
        float Wu[5];
#pragma unroll
        for (int j = 0; j < 5; j++) Wu[j] = 2.0f * BVAL * e[j] / s;
        float m2 = Wu[0];
#pragma unroll
        for (int j = 1; j < 5; j++) m2 = fmaxf(m2, Wu[j]);
        float e2[5], s2 = 0.f;
#pragma unroll
        for (int j = 0; j < 5; j++) { e2[j] = expf(Wu[j] - m2); s2 += e2[j]; }
        cw[0] = -BVAL;
        float run = 0.f;
#pragma unroll
        for (int j = 0; j < 5; j++) {
            float w = MIN_BW + (1.0f - MIN_BW * KBINS) * (e2[j] / s2);
            run += w;
            cw[j + 1] = 2.0f * BVAL * run - BVAL;
        }
        cw[5] = BVAL;
#pragma unroll
        for (int j = 0; j < 5; j++) wd[j] = cw[j + 1] - cw[j];
    }

    float ch[6], hd[5];
    {
        float m = raw[5];
#pragma unroll
        for (int j = 1; j < 5; j++) m = fmaxf(m, raw[5 + j]);
        float e[5], s = 0.f;
#pragma unroll
        for (int j = 0; j < 5; j++) { e[j] = expf(raw[5 + j] - m); s += e[j]; }
        float Hu[5];
#pragma unroll
        for (int j = 0; j < 5; j++) Hu[j] = 2.0f * BVAL * e[j] / s;
        float m2 = Hu[0];
#pragma unroll
        for (int j = 1; j < 5; j++) m2 = fmaxf(m2, Hu[j]);
        float e2[5], s2 = 0.f;
#pragma unroll
        for (int j = 0; j < 5; j++) { e2[j] = expf(Hu[j] - m2); s2 += e2[j]; }
        ch[0] = -BVAL;
        float run = 0.f;
#pragma unroll
        for (int j = 0; j < 5; j++) {
            float h = MIN_BH + (1.0f - MIN_BH * KBINS) * (e2[j] / s2);
            run += h;
            ch[j + 1] = 2.0f * BVAL * run - BVAL;
        }
        ch[5] = BVAL;
#pragma unroll
        for (int j = 0; j < 5; j++) hd[j] = ch[j + 1] - ch[j];
    }

    float deriv[6];
    deriv[0] = 1.0f;
    deriv[5] = 1.0f;
#pragma unroll
    for (int j = 0; j < 4; j++) {
        float du = softplusf(raw[10 + j]);
        deriv[j + 1] = MIN_DV + softplusf(du);
    }

    const float xc = fminf(fmaxf(t, -BVAL), BVAL);
    int cnt = 0;
#pragma unroll
    for (int j = 0; j < 6; j++) cnt += (xc >= cw[j]) ? 1 : 0;
    int idx = min(max(cnt - 1, 0), 4);

    const float icw = cw[idx], iw = wd[idx];
    const float ich = ch[idx], ih = hd[idx];
    const float delta = ih / iw;
    const float dk = deriv[idx], dk1 = deriv[idx + 1];
    const float theta = (xc - icw) / iw;
    const float t1m = theta * (1.0f - theta);
    const float num = ih * (delta * theta * theta + dk * t1m);
    const float den = delta + (dk + dk1 - 2.0f * delta) * t1m;
    const float y = ich + num / den;
    const float omt = 1.0f - theta;
    const float dnum = delta * delta * (dk1 * theta * theta + 2.0f * delta * t1m + dk * omt * omt);
    const float ld = logf(dnum) - 2.0f * logf(den);

    const bool inside = (t >= -BVAL) && (t <= BVAL);
    const float outv = inside ? y : t;
    const float ldv  = inside ? ld : 0.0f;

    z[(size_t)n * 256 + zoff + d] = outv;

    __shared__ float red[128];
    red[d] = ldv;
    __syncthreads();
#pragma unroll
    for (int s = 64; s > 0; s >>= 1) {
        if (d < s) red[d] += red[d + s];
        __syncthreads();
    }
    if (d == 0) {
        if (add) logdet[n] += red[0];
        else     logdet[n]  = red[0];
    }
}

// ======================= host side =======================
extern "C" void kernel_launch(void* const* d_in, const int* in_sizes, int n_in,
                              void* d_out, int out_size)
{
    const float* x     = (const float*)d_in[0];
    const float* f0_w0 = (const float*)d_in[1];
    const float* f0_b0 = (const float*)d_in[2];
    const float* f0_w1 = (const float*)d_in[3];
    const float* f0_b1 = (const float*)d_in[4];
    const float* f1_w0 = (const float*)d_in[5];
    const float* f1_b0 = (const float*)d_in[6];
    const float* f1_w1 = (const float*)d_in[7];
    const float* f1_b1 = (const float*)d_in[8];

    const int N = in_sizes[0] / 256;              // 32768
    float* z      = (float*)d_out;
    float* logdet = z + (size_t)N * 256;

    uint32_t *xsb, *xss, *hb, *hs, *w0b, *w0s, *w1b, *w1s;
    float* params;
    cudaGetSymbolAddress((void**)&xsb, g_xs_big);
    cudaGetSymbolAddress((void**)&xss, g_xs_sml);
    cudaGetSymbolAddress((void**)&hb,  g_h_big);
    cudaGetSymbolAddress((void**)&hs,  g_h_sml);
    cudaGetSymbolAddress((void**)&params, g_params);
    cudaGetSymbolAddress((void**)&w0b, g_w0b);
    cudaGetSymbolAddress((void**)&w0s, g_w0s);
    cudaGetSymbolAddress((void**)&w1b, g_w1b);
    cudaGetSymbolAddress((void**)&w1s, g_w1s);

    cudaFuncSetAttribute(gemm_h3<0>, cudaFuncAttributeMaxDynamicSharedMemorySize, GEMM_SMEM);
    cudaFuncSetAttribute(gemm_h3<1>, cudaFuncAttributeMaxDynamicSharedMemorySize, GEMM_SMEM);

    const dim3 g1(512 / 128, N / 128);    // (4, 256)
    const dim3 g2(1792 / 128, N / 128);   // (14, 256)
    const int nConvBlocks = N * 64 / 256; // 8192

    // ---- coupling 1 (launch #4 = big GEMM, targeted by ncu capture) ----
    conv_all<<<480 + nConvBlocks, 256>>>(x, 0, f0_w0, f0_w1,
                                         w0b, w0s, w1b, w1s, xsb, xss);          // 1
    gemm_h3<1><<<g1, 128, GEMM_SMEM>>>(xsb, xss, w0b, w0s, f0_b0,
                                       nullptr, hb, hs, 512, 64);                // 2
    conv_all<<<480, 256>>>(x, 0, f1_w0, f1_w1,
                           w0b + 512 * 64, w0s + 512 * 64,
                           w1b + 1792 * 256, w1s + 1792 * 256, xsb, xss);        // 3 (weights only)
    gemm_h3<0><<<g2, 128, GEMM_SMEM>>>(hb, hs, w1b, w1s, f0_b1,
                                       params, nullptr, nullptr, 1792, 256);     // 4 <- profiled
    spline_kernel<<<N, 128>>>(x, 128, params, z, 128, logdet, 0);                // 5

    // ---- coupling 2 ----
    conv_x<<<nConvBlocks, 256>>>(z, 128, xsb, xss);                              // 6
    gemm_h3<1><<<g1, 128, GEMM_SMEM>>>(xsb, xss, w0b + 512 * 64, w0s + 512 * 64,
                                       f1_b0, nullptr, hb, hs, 512, 64);         // 7
    gemm_h3<0><<<g2, 128, GEMM_SMEM>>>(hb, hs, w1b + 1792 * 256, w1s + 1792 * 256,
                                       f1_b1, params, nullptr, nullptr, 1792, 256); // 8
    spline_kernel<<<N, 128>>>(x, 0, params, z, 0, logdet, 1);                    // 9
}

// round 11
// speedup vs baseline: 1.0796x; 1.0796x over previous
#include <cuda_runtime.h>
#include <cuda_fp16.h>
#include <math.h>
#include <stdint.h>

// ---------------- scratch (allocation-free: __device__ globals) ----------------
__device__ __align__(1024) uint32_t g_xs_big[32768ULL * 64];
__device__ __align__(1024) uint32_t g_xs_sml[32768ULL * 64];
__device__ __align__(1024) uint32_t g_h_big[32768ULL * 256];
__device__ __align__(1024) uint32_t g_h_sml[32768ULL * 256];
__device__ __align__(1024) float    g_params[32768ULL * 1792];
__device__ __align__(1024) uint32_t g_w0b[2][512 * 64];
__device__ __align__(1024) uint32_t g_w0s[2][512 * 64];
__device__ __align__(1024) uint32_t g_w1b[2][1792 * 256];
__device__ __align__(1024) uint32_t g_w1s[2][1792 * 256];

#define BVAL   3.0f
#define KBINS  5
#define MIN_BW 0.001f
#define MIN_BH 0.001f
#define MIN_DV 0.001f

// ======================= helpers =======================
__device__ __forceinline__ int gidx(int kpg) {
    return (kpg & ~15) | ((kpg & 3) << 2) | ((kpg >> 2) & 3);
}

__device__ __forceinline__ void split2h(float x0, float x1, uint32_t& b, uint32_t& s) {
    __half b0 = __float2half_rn(x0);
    __half b1 = __float2half_rn(x1);
    float r0 = x0 - __half2float(b0);
    float r1 = x1 - __half2float(b1);
    __half s0 = __float2half_rn(r0);
    __half s1 = __float2half_rn(r1);
    b = (uint32_t)__half_as_ushort(b0) | ((uint32_t)__half_as_ushort(b1) << 16);
    s = (uint32_t)__half_as_ushort(s0) | ((uint32_t)__half_as_ushort(s1) << 16);
}

// fp16 inputs, fp32 accumulator (main term; rt ~8/SMSP)
__device__ __forceinline__ void mma_h_f32(float* d,
                                          uint32_t a0, uint32_t a1, uint32_t a2, uint32_t a3,
                                          uint32_t b0, uint32_t b1) {
    asm volatile(
        "mma.sync.aligned.m16n8k16.row.col.f32.f16.f16.f32 "
        "{%0,%1,%2,%3}, {%4,%5,%6,%7}, {%8,%9}, {%0,%1,%2,%3};"
        : "+f"(d[0]), "+f"(d[1]), "+f"(d[2]), "+f"(d[3])
        : "r"(a0), "r"(a1), "r"(a2), "r"(a3), "r"(b0), "r"(b1));
}
// fp16 inputs, fp16 accumulator (correction terms; 2x issue rate)
__device__ __forceinline__ void mma_h_f16(uint32_t* d,
                                          uint32_t a0, uint32_t a1, uint32_t a2, uint32_t a3,
                                          uint32_t b0, uint32_t b1) {
    asm volatile(
        "mma.sync.aligned.m16n8k16.row.col.f16.f16.f16.f16 "
        "{%0,%1}, {%2,%3,%4,%5}, {%6,%7}, {%0,%1};"
        : "+r"(d[0]), "+r"(d[1])
        : "r"(a0), "r"(a1), "r"(a2), "r"(a3), "r"(b0), "r"(b1));
}

#define CP16(dst, src) \
    asm volatile("cp.async.cg.shared.global [%0], [%1], 16;" :: "r"(dst), "l"(src) : "memory")
#define CP_COMMIT() asm volatile("cp.async.commit_group;" ::: "memory")
#define CP_WAIT1()  asm volatile("cp.async.wait_group 1;" ::: "memory")
#define CP_WAIT0()  asm volatile("cp.async.wait_group 0;" ::: "memory")

__device__ __forceinline__ uint32_t smem_u32(const void* p) {
    uint32_t a;
    asm("{ .reg .u64 t; cvta.to.shared.u64 t, %1; cvt.u32.u64 %0, t; }" : "=r"(a) : "l"(p));
    return a;
}

// ======================= converters =======================
__device__ __forceinline__ void conv_w_body(
    const float* __restrict__ w, int M, int K2, int m0, int kp0,
    uint32_t* __restrict__ ob, uint32_t* __restrict__ os,
    uint32_t (*tb)[33], uint32_t (*ts)[33], int tid)
{
    const int xx = tid & 31, yy = tid >> 5;
    for (int i = yy; i < 32; i += 8) {
        int kpg = kp0 + i, m = m0 + xx;
        float v0 = w[(size_t)(2 * kpg) * M + m];
        float v1 = w[(size_t)(2 * kpg + 1) * M + m];
        split2h(v0, v1, tb[i][xx], ts[i][xx]);
    }
    __syncthreads();
    for (int i = yy; i < 32; i += 8) {
        int m = m0 + i;
        size_t dst = (size_t)m * K2 + gidx(kp0 + xx);
        ob[dst] = tb[xx][i]; os[dst] = ts[xx][i];
    }
}

__global__ void __launch_bounds__(256) conv_all(
    const float* __restrict__ x, int xoff,
    const float* __restrict__ w0, const float* __restrict__ w1,
    uint32_t* __restrict__ w0bD, uint32_t* __restrict__ w0sD,
    uint32_t* __restrict__ w1bD, uint32_t* __restrict__ w1sD,
    uint32_t* __restrict__ xb, uint32_t* __restrict__ xs)
{
    __shared__ uint32_t tb[32][33], ts[32][33];
    const int bid = blockIdx.x;
    const int tid = threadIdx.x;
    if (bid < 32) {
        conv_w_body(w0, 512, 64, (bid & 15) * 32, (bid >> 4) * 32, w0bD, w0sD, tb, ts, tid);
    } else if (bid < 480) {
        int b = bid - 32;
        conv_w_body(w1, 1792, 256, (b % 56) * 32, (b / 56) * 32, w1bD, w1sD, tb, ts, tid);
    } else {
        int t = (bid - 480) * 256 + tid;
        int row = t >> 6, kpg = t & 63;
        float2 v = *(const float2*)(x + (size_t)row * 256 + xoff + 2 * kpg);
        uint32_t b_, s_;
        split2h(v.x, v.y, b_, s_);
        int dst = row * 64 + gidx(kpg);
        xb[dst] = b_; xs[dst] = s_;
    }
}

__global__ void __launch_bounds__(256) conv_x(const float* __restrict__ x, int xoff,
                                              uint32_t* __restrict__ ob,
                                              uint32_t* __restrict__ os) {
    int t = blockIdx.x * 256 + threadIdx.x;
    int row = t >> 6, kpg = t & 63;
    float2 v = *(const float2*)(x + (size_t)row * 256 + xoff + 2 * kpg);
    uint32_t b, s;
    split2h(v.x, v.y, b, s);
    int dst = row * 64 + gidx(kpg);
    ob[dst] = b; os[dst] = s;
}

// ======================= fp16x3 mixed-acc tensor-core GEMM =======================
// Block 128x128 (BK=16 words=32k), 256 threads (8 warps 2x4), warp 64x32.
// Main term (Ab*Bb) in f32 acc; corrections (As*Bb + Ab*Bs) share ONE f16 acc
// (2x issue rate). Per-mt phases keep only one A-fragment set live:
//   load Ab -> term1(f32,bb) + term3(f16,bs);  load As -> term2(f16,bb).
#define GEMM_SMEM (3 * 32768)

template <int EPI>
__global__ void __launch_bounds__(256, 2) gemm_h3(
    const uint32_t* __restrict__ Ab, const uint32_t* __restrict__ As,
    const uint32_t* __restrict__ Bb, const uint32_t* __restrict__ Bs,
    const float* __restrict__ bias,
    float* __restrict__ C, uint32_t* __restrict__ Hb, uint32_t* __restrict__ Hs,
    int M, int K2)
{
    extern __shared__ uint32_t sm[];
    const uint32_t sbase = smem_u32(sm);
    const int tid  = threadIdx.x;
    const int lane = tid & 31;
    const int wid  = tid >> 5;
    const int warp_m = wid & 1;
    const int warp_n = wid >> 1;
    const int rowBase = blockIdx.y * 128;
    const int colBase = blockIdx.x * 128;
    const int q  = lane & 3;
    const int rw = lane >> 2;

    const int cr  = tid >> 1;
    const int cw8 = (tid & 1) * 8;
    const uint32_t* gAb = Ab + (size_t)(rowBase + cr) * K2 + cw8;
    const uint32_t* gAs = As + (size_t)(rowBase + cr) * K2 + cw8;
    const uint32_t* gBb = Bb + (size_t)(colBase + cr) * K2 + cw8;
    const uint32_t* gBs = Bs + (size_t)(colBase + cr) * K2 + cw8;
    const uint32_t sdst = sbase + (uint32_t)(cr * 16 + cw8) * 4;

#define STAGE(it, buf) do { \
        uint32_t d0 = sdst + (uint32_t)(buf) * 32768u; \
        const uint32_t* pa = gAb + (it) * 16; \
        const uint32_t* ps = gAs + (it) * 16; \
        const uint32_t* pb = gBb + (it) * 16; \
        const uint32_t* pq = gBs + (it) * 16; \
        CP16(d0,          pa); CP16(d0 + 16,          pa + 4); \
        CP16(d0 + 8192,   ps); CP16(d0 + 8192 + 16,   ps + 4); \
        CP16(d0 + 16384,  pb); CP16(d0 + 16384 + 16,  pb + 4); \
        CP16(d0 + 24576,  pq); CP16(d0 + 24576 + 16,  pq + 4); \
        CP_COMMIT(); \
    } while (0)

    float    accf[4][4][4];   // main term, f32
    uint32_t acch[4][4][2];   // corrections, f16x2 pairs
#pragma unroll
    for (int mt = 0; mt < 4; mt++)
#pragma unroll
        for (int nt = 0; nt < 4; nt++) {
#pragma unroll
            for (int c = 0; c < 4; c++) accf[mt][nt][c] = 0.f;
            acch[mt][nt][0] = 0u; acch[mt][nt][1] = 0u;
        }

    const int nIter = K2 >> 4;
    STAGE(0, 0);
    STAGE(1, 1);

    int buf = 0;
    for (int it = 0; it < nIter; it++) {
        if (it + 1 < nIter) { CP_WAIT1(); } else { CP_WAIT0(); }
        __syncthreads();
        if (it + 2 < nIter) {
            int nb = buf + 2; if (nb >= 3) nb -= 3;
            STAGE(it + 2, nb);
        }
        const uint32_t* sA = sm + buf * 8192;
        const uint32_t* sB = sA + 4096;

        uint4 bb[4], bs[4];
#pragma unroll
        for (int nt = 0; nt < 4; nt++) {
            const uint32_t* p = sB + (warp_n * 32 + nt * 8 + rw) * 16 + 4 * q;
            bb[nt] = *(const uint4*)p;
            bs[nt] = *(const uint4*)(p + 2048);
        }

#pragma unroll
        for (int mt = 0; mt < 4; mt++) {
            const uint32_t* p = sA + (warp_m * 64 + mt * 16 + rw) * 16 + 4 * q;
            // ---- phase A: A-big fragments ----
            {
                uint4 alo = *(const uint4*)p;
                uint4 ahi = *(const uint4*)(p + 128);
                // term 1: Ab*Bb -> f32 acc (ks0, ks1)
#pragma unroll
                for (int nt = 0; nt < 4; nt++)
                    mma_h_f32(accf[mt][nt], alo.x, ahi.x, alo.y, ahi.y, bb[nt].x, bb[nt].y);
#pragma unroll
                for (int nt = 0; nt < 4; nt++)
                    mma_h_f32(accf[mt][nt], alo.z, ahi.z, alo.w, ahi.w, bb[nt].z, bb[nt].w);
                // term 3: Ab*Bs -> f16 acc
#pragma unroll
                for (int nt = 0; nt < 4; nt++)
                    mma_h_f16(acch[mt][nt], alo.x, ahi.x, alo.y, ahi.y, bs[nt].x, bs[nt].y);
#pragma unroll
                for (int nt = 0; nt < 4; nt++)
                    mma_h_f16(acch[mt][nt], alo.z, ahi.z, alo.w, ahi.w, bs[nt].z, bs[nt].w);
            }
            // ---- phase B: A-small fragments (reuse registers) ----
            {
                uint4 slo = *(const uint4*)(p + 2048);
                uint4 shi = *(const uint4*)(p + 2048 + 128);
                // term 2: As*Bb -> f16 acc
#pragma unroll
                for (int nt = 0; nt < 4; nt++)
                    mma_h_f16(acch[mt][nt], slo.x, shi.x, slo.y, shi.y, bb[nt].x, bb[nt].y);
#pragma unroll
                for (int nt = 0; nt < 4; nt++)
                    mma_h_f16(acch[mt][nt], slo.z, shi.z, slo.w, shi.w, bb[nt].z, bb[nt].w);
            }
        }
        buf++; if (buf >= 3) buf -= 3;
    }

    // ---- epilogue: main + correction + bias ----
#pragma unroll
    for (int mt = 0; mt < 4; mt++) {
#pragma unroll
        for (int nt = 0; nt < 4; nt++) {
            int row = rowBase + warp_m * 64 + mt * 16 + rw;
            int col = colBase + warp_n * 32 + nt * 8 + q * 2;
            float2 c01 = __half22float2(*(const __half2*)&acch[mt][nt][0]);
            float2 c23 = __half22float2(*(const __half2*)&acch[mt][nt][1]);
            float b0 = bias[col], b1 = bias[col + 1];
            float v0 = accf[mt][nt][0] + c01.x + b0;
            float v1 = accf[mt][nt][1] + c01.y + b1;
            float v2 = accf[mt][nt][2] + c23.x + b0;
            float v3 = accf[mt][nt][3] + c23.y + b1;
            if (EPI == 1) {
                v0 = tanhf(v0); v1 = tanhf(v1); v2 = tanhf(v2); v3 = tanhf(v3);
                int dcol = gidx(col >> 1);
                uint32_t bbv, ssv;
                split2h(v0, v1, bbv, ssv);
                Hb[(size_t)row * (M >> 1) + dcol] = bbv;
                Hs[(size_t)row * (M >> 1) + dcol] = ssv;
                split2h(v2, v3, bbv, ssv);
                Hb[(size_t)(row + 8) * (M >> 1) + dcol] = bbv;
                Hs[(size_t)(row + 8) * (M >> 1) + dcol] = ssv;
            } else {
                *(float2*)&C[(size_t)row * M + col]       = make_float2(v0, v1);
                *(float2*)&C[(size_t)(row + 8) * M + col] = make_float2(v2, v3);
            }
        }
    }
#undef STAGE
}

// ======================= spline =======================
__device__ __forceinline__ float softplusf(float x) {
    return (x > 20.0f) ? x : log1pf(expf(x));
}

__global__ void __launch_bounds__(128) spline_kernel(
    const float* __restrict__ xin, int xoff,
    const float* __restrict__ params,
    float* __restrict__ z, int zoff,
    float* __restrict__ logdet, int add)
{
    const int n = blockIdx.x;
    const int d = threadIdx.x;

    __shared__ float ps[1792];
    {
        const float4* src = (const float4*)(params + (size_t)n * 1792);
#pragma unroll
        for (int i = 0; i < 3; i++)
            *(float4*)&ps[(d + i * 128) * 4] = src[d + i * 128];
        if (d < 64) *(float4*)&ps[(d + 384) * 4] = src[d + 384];
    }
    __syncthreads();

    float raw[14];
#pragma unroll
    for (int j = 0; j < 14; j++) raw[j] = ps[d * 14 + j];

    const float t = xin[(size_t)n * 256 + xoff + d];

    float cw[6], wd[5];
    {
        float m = raw[0];
#pragma unroll
        for (int j = 1; j < 5; j++) m = fmaxf(m, raw[j]);
        float e[5], s = 0.f;
#pragma unroll
        for (int j = 0; j < 5; j++) { e[j] = expf(raw[j] - m); s += e[j]; }
        float Wu[5];
#pragma unroll
        for (int j = 0; j < 5; j++) Wu[j] = 2.0f * BVAL * e[j] / s;
        float m2 = Wu[0];
#pragma unroll
        for (int j = 1; j < 5; j++) m2 = fmaxf(m2, Wu[j]);
        float e2[5], s2 = 0.f;
#pragma unroll
        for (int j = 0; j < 5; j++) { e2[j] = expf(Wu[j] - m2); s2 += e2[j]; }
        cw[0] = -BVAL;
        float run = 0.f;
#pragma unroll
        for (int j = 0; j < 5; j++) {
            float w = MIN_BW + (1.0f - MIN_BW * KBINS) * (e2[j] / s2);
            run += w;
            cw[j + 1] = 2.0f * BVAL * run - BVAL;
        }
        cw[5] = BVAL;
#pragma unroll
        for (int j = 0; j < 5; j++) wd[j] = cw[j + 1] - cw[j];
    }

    float ch[6], hd[5];
    {
        float m = raw[5];
#pragma unroll
        for (int j = 1; j < 5; j++) m = fmaxf(m, raw[5 + j]);
        float e[5], s = 0.f;
#pragma unroll
        for (int j = 0; j < 5; j++) { e[j] = expf(raw[5 + j] - m); s += e[j]; }
        float Hu[5];
#pragma unroll
        for (int j = 0; j < 5; j++) Hu[j] = 2.0f * BVAL * e[j] / s;
        float m2 = Hu[0];
#pragma unroll
        for (int j = 1; j < 5; j++) m2 = fmaxf(m2, Hu[j]);
        float e2[5], s2 = 0.f;
#pragma unroll
        for (int j = 0; j < 5; j++) { e2[j] = expf(Hu[j] - m2); s2 += e2[j]; }
        ch[0] = -BVAL;
        float run = 0.f;
#pragma unroll
        for (int j = 0; j < 5; j++) {
            float h = MIN_BH + (1.0f - MIN_BH * KBINS) * (e2[j] / s2);
            run += h;
            ch[j + 1] = 2.0f * BVAL * run - BVAL;
        }
        ch[5] = BVAL;
#pragma unroll
        for (int j = 0; j < 5; j++) hd[j] = ch[j + 1] - ch[j];
    }

    float deriv[6];
    deriv[0] = 1.0f;
    deriv[5] = 1.0f;
#pragma unroll
    for (int j = 0; j < 4; j++) {
        float du = softplusf(raw[10 + j]);
        deriv[j + 1] = MIN_DV + softplusf(du);
    }

    const float xc = fminf(fmaxf(t, -BVAL), BVAL);
    int cnt = 0;
#pragma unroll
    for (int j = 0; j < 6; j++) cnt += (xc >= cw[j]) ? 1 : 0;
    int idx = min(max(cnt - 1, 0), 4);

    const float icw = cw[idx], iw = wd[idx];
    const float ich = ch[idx], ih = hd[idx];
    const float delta = ih / iw;
    const float dk = deriv[idx], dk1 = deriv[idx + 1];
    const float theta = (xc - icw) / iw;
    const float t1m = theta * (1.0f - theta);
    const float num = ih * (delta * theta * theta + dk * t1m);
    const float den = delta + (dk + dk1 - 2.0f * delta) * t1m;
    const float y = ich + num / den;
    const float omt = 1.0f - theta;
    const float dnum = delta * delta * (dk1 * theta * theta + 2.0f * delta * t1m + dk * omt * omt);
    const float ld = logf(dnum) - 2.0f * logf(den);

    const bool inside = (t >= -BVAL) && (t <= BVAL);
    const float outv = inside ? y : t;
    const float ldv  = inside ? ld : 0.0f;

    z[(size_t)n * 256 + zoff + d] = outv;

    __shared__ float red[128];
    red[d] = ldv;
    __syncthreads();
#pragma unroll
    for (int s = 64; s > 0; s >>= 1) {
        if (d < s) red[d] += red[d + s];
        __syncthreads();
    }
    if (d == 0) {
        if (add) logdet[n] += red[0];
        else     logdet[n]  = red[0];
    }
}

// ======================= host side =======================
extern "C" void kernel_launch(void* const* d_in, const int* in_sizes, int n_in,
                              void* d_out, int out_size)
{
    const float* x     = (const float*)d_in[0];
    const float* f0_w0 = (const float*)d_in[1];
    const float* f0_b0 = (const float*)d_in[2];
    const float* f0_w1 = (const float*)d_in[3];
    const float* f0_b1 = (const float*)d_in[4];
    const float* f1_w0 = (const float*)d_in[5];
    const float* f1_b0 = (const float*)d_in[6];
    const float* f1_w1 = (const float*)d_in[7];
    const float* f1_b1 = (const float*)d_in[8];

    const int N = in_sizes[0] / 256;              // 32768
    float* z      = (float*)d_out;
    float* logdet = z + (size_t)N * 256;

    uint32_t *xsb, *xss, *hb, *hs, *w0b, *w0s, *w1b, *w1s;
    float* params;
    cudaGetSymbolAddress((void**)&xsb, g_xs_big);
    cudaGetSymbolAddress((void**)&xss, g_xs_sml);
    cudaGetSymbolAddress((void**)&hb,  g_h_big);
    cudaGetSymbolAddress((void**)&hs,  g_h_sml);
    cudaGetSymbolAddress((void**)&params, g_params);
    cudaGetSymbolAddress((void**)&w0b, g_w0b);
    cudaGetSymbolAddress((void**)&w0s, g_w0s);
    cudaGetSymbolAddress((void**)&w1b, g_w1b);
    cudaGetSymbolAddress((void**)&w1s, g_w1s);

    cudaFuncSetAttribute(gemm_h3<0>, cudaFuncAttributeMaxDynamicSharedMemorySize, GEMM_SMEM);
    cudaFuncSetAttribute(gemm_h3<1>, cudaFuncAttributeMaxDynamicSharedMemorySize, GEMM_SMEM);

    const dim3 g1(512 / 128, N / 128);    // (4, 256)
    const dim3 g2(1792 / 128, N / 128);   // (14, 256)
    const int nConvBlocks = N * 64 / 256; // 8192

    // ---- coupling 1 (launch #4 = big GEMM, targeted by ncu capture) ----
    conv_all<<<480 + nConvBlocks, 256>>>(x, 0, f0_w0, f0_w1,
                                         w0b, w0s, w1b, w1s, xsb, xss);          // 1
    gemm_h3<1><<<g1, 256, GEMM_SMEM>>>(xsb, xss, w0b, w0s, f0_b0,
                                       nullptr, hb, hs, 512, 64);                // 2
    conv_all<<<480, 256>>>(x, 0, f1_w0, f1_w1,
                           w0b + 512 * 64, w0s + 512 * 64,
                           w1b + 1792 * 256, w1s + 1792 * 256, xsb, xss);        // 3 (weights only)
    gemm_h3<0><<<g2, 256, GEMM_SMEM>>>(hb, hs, w1b, w1s, f0_b1,
                                       params, nullptr, nullptr, 1792, 256);     // 4 <- profiled
    spline_kernel<<<N, 128>>>(x, 128, params, z, 128, logdet, 0);                // 5

    // ---- coupling 2 ----
    conv_x<<<nConvBlocks, 256>>>(z, 128, xsb, xss);                              // 6
    gemm_h3<1><<<g1, 256, GEMM_SMEM>>>(xsb, xss, w0b + 512 * 64, w0s + 512 * 64,
                                       f1_b0, nullptr, hb, hs, 512, 64);         // 7
    gemm_h3<0><<<g2, 256, GEMM_SMEM>>>(hb, hs, w1b + 1792 * 256, w1s + 1792 * 256,
                                       f1_b1, params, nullptr, nullptr, 1792, 256); // 8
    spline_kernel<<<N, 128>>>(x, 0, params, z, 0, logdet, 1);                    // 9
}

// round 12
// speedup vs baseline: 1.5497x; 1.4354x over previous
#include <cuda_runtime.h>
#include <cuda_fp16.h>
#include <math.h>
#include <stdint.h>

// ---------------- scratch (allocation-free: __device__ globals) ----------------
__device__ __align__(1024) uint32_t g_xs_big[32768ULL * 64];
__device__ __align__(1024) uint32_t g_xs_sml[32768ULL * 64];
__device__ __align__(1024) uint32_t g_h_big[32768ULL * 256];
__device__ __align__(1024) uint32_t g_h_sml[32768ULL * 256];
__device__ __align__(1024) float    g_params[32768ULL * 1792];
__device__ __align__(1024) uint32_t g_w0b[2][512 * 64];
__device__ __align__(1024) uint32_t g_w0s[2][512 * 64];
__device__ __align__(1024) uint32_t g_w1b[2][1792 * 256];
__device__ __align__(1024) uint32_t g_w1s[2][1792 * 256];

#define BVAL   3.0f
#define KBINS  5
#define MIN_BW 0.001f
#define MIN_BH 0.001f
#define MIN_DV 0.001f

// ======================= helpers =======================
__device__ __forceinline__ int gidx(int kpg) {
    return (kpg & ~15) | ((kpg & 3) << 2) | ((kpg >> 2) & 3);
}

__device__ __forceinline__ void split2h(float x0, float x1, uint32_t& b, uint32_t& s) {
    __half b0 = __float2half_rn(x0);
    __half b1 = __float2half_rn(x1);
    float r0 = x0 - __half2float(b0);
    float r1 = x1 - __half2float(b1);
    __half s0 = __float2half_rn(r0);
    __half s1 = __float2half_rn(r1);
    b = (uint32_t)__half_as_ushort(b0) | ((uint32_t)__half_as_ushort(b1) << 16);
    s = (uint32_t)__half_as_ushort(s0) | ((uint32_t)__half_as_ushort(s1) << 16);
}

__device__ __forceinline__ void mma_h(float* d,
                                      uint32_t a0, uint32_t a1, uint32_t a2, uint32_t a3,
                                      uint32_t b0, uint32_t b1) {
    asm volatile(
        "mma.sync.aligned.m16n8k16.row.col.f32.f16.f16.f32 "
        "{%0,%1,%2,%3}, {%4,%5,%6,%7}, {%8,%9}, {%0,%1,%2,%3};"
        : "+f"(d[0]), "+f"(d[1]), "+f"(d[2]), "+f"(d[3])
        : "r"(a0), "r"(a1), "r"(a2), "r"(a3), "r"(b0), "r"(b1));
}

#define CP16(dst, src) \
    asm volatile("cp.async.cg.shared.global [%0], [%1], 16;" :: "r"(dst), "l"(src) : "memory")
#define CP_COMMIT() asm volatile("cp.async.commit_group;" ::: "memory")
#define CP_WAIT1()  asm volatile("cp.async.wait_group 1;" ::: "memory")
#define CP_WAIT0()  asm volatile("cp.async.wait_group 0;" ::: "memory")

__device__ __forceinline__ uint32_t smem_u32(const void* p) {
    uint32_t a;
    asm("{ .reg .u64 t; cvta.to.shared.u64 t, %1; cvt.u32.u64 %0, t; }" : "=r"(a) : "l"(p));
    return a;
}

// ======================= converters =======================
__device__ __forceinline__ void conv_w_body(
    const float* __restrict__ w, int M, int K2, int m0, int kp0,
    uint32_t* __restrict__ ob, uint32_t* __restrict__ os,
    uint32_t (*tb)[33], uint32_t (*ts)[33], int tid)
{
    const int xx = tid & 31, yy = tid >> 5;
    for (int i = yy; i < 32; i += 8) {
        int kpg = kp0 + i, m = m0 + xx;
        float v0 = w[(size_t)(2 * kpg) * M + m];
        float v1 = w[(size_t)(2 * kpg + 1) * M + m];
        split2h(v0, v1, tb[i][xx], ts[i][xx]);
    }
    __syncthreads();
    for (int i = yy; i < 32; i += 8) {
        int m = m0 + i;
        size_t dst = (size_t)m * K2 + gidx(kp0 + xx);
        ob[dst] = tb[xx][i]; os[dst] = ts[xx][i];
    }
}

__global__ void __launch_bounds__(256) conv_all(
    const float* __restrict__ x, int xoff,
    const float* __restrict__ w0, const float* __restrict__ w1,
    uint32_t* __restrict__ w0bD, uint32_t* __restrict__ w0sD,
    uint32_t* __restrict__ w1bD, uint32_t* __restrict__ w1sD,
    uint32_t* __restrict__ xb, uint32_t* __restrict__ xs)
{
    __shared__ uint32_t tb[32][33], ts[32][33];
    const int bid = blockIdx.x;
    const int tid = threadIdx.x;
    if (bid < 32) {
        conv_w_body(w0, 512, 64, (bid & 15) * 32, (bid >> 4) * 32, w0bD, w0sD, tb, ts, tid);
    } else if (bid < 480) {
        int b = bid - 32;
        conv_w_body(w1, 1792, 256, (b % 56) * 32, (b / 56) * 32, w1bD, w1sD, tb, ts, tid);
    } else {
        int t = (bid - 480) * 256 + tid;
        int row = t >> 6, kpg = t & 63;
        float2 v = *(const float2*)(x + (size_t)row * 256 + xoff + 2 * kpg);
        uint32_t b_, s_;
        split2h(v.x, v.y, b_, s_);
        int dst = row * 64 + gidx(kpg);
        xb[dst] = b_; xs[dst] = s_;
    }
}

__global__ void __launch_bounds__(256) conv_x(const float* __restrict__ x, int xoff,
                                              uint32_t* __restrict__ ob,
                                              uint32_t* __restrict__ os) {
    int t = blockIdx.x * 256 + threadIdx.x;
    int row = t >> 6, kpg = t & 63;
    float2 v = *(const float2*)(x + (size_t)row * 256 + xoff + 2 * kpg);
    uint32_t b, s;
    split2h(v.x, v.y, b, s);
    int dst = row * 64 + gidx(kpg);
    ob[dst] = b; os[dst] = s;
}

// ======================= fp16 split tensor-core GEMM =======================
// Block 128x128 (BK=16 words=32k), 256 threads (8 warps 2x4), warp 64x32.
// TERM3=1: full 3-term (Ab*Bb + As*Bb + Ab*Bs)  — used for GEMM1 (accuracy).
// TERM3=0: 2-term   (Ab*Bb + As*Bb)             — used for GEMM2 (speed; the
//          dropped Ab*Bs is ~2^-12 relative). Bs is neither staged nor loaded.
#define GEMM_SMEM (3 * 32768)

template <int EPI, int TERM3>
__global__ void __launch_bounds__(256, 2) gemm_h3(
    const uint32_t* __restrict__ Ab, const uint32_t* __restrict__ As,
    const uint32_t* __restrict__ Bb, const uint32_t* __restrict__ Bs,
    const float* __restrict__ bias,
    float* __restrict__ C, uint32_t* __restrict__ Hb, uint32_t* __restrict__ Hs,
    int M, int K2)
{
    extern __shared__ uint32_t sm[];
    const uint32_t sbase = smem_u32(sm);
    const int tid  = threadIdx.x;
    const int lane = tid & 31;
    const int wid  = tid >> 5;
    const int warp_m = wid & 1;
    const int warp_n = wid >> 1;
    const int rowBase = blockIdx.y * 128;
    const int colBase = blockIdx.x * 128;
    const int q  = lane & 3;
    const int rw = lane >> 2;

    const int cr  = tid >> 1;
    const int cw8 = (tid & 1) * 8;
    const uint32_t* gAb = Ab + (size_t)(rowBase + cr) * K2 + cw8;
    const uint32_t* gAs = As + (size_t)(rowBase + cr) * K2 + cw8;
    const uint32_t* gBb = Bb + (size_t)(colBase + cr) * K2 + cw8;
    const uint32_t* gBs = Bs + (size_t)(colBase + cr) * K2 + cw8;
    const uint32_t sdst = sbase + (uint32_t)(cr * 16 + cw8) * 4;

#define STAGE(it, buf) do { \
        uint32_t d0 = sdst + (uint32_t)(buf) * 32768u; \
        const uint32_t* pa = gAb + (it) * 16; \
        const uint32_t* ps = gAs + (it) * 16; \
        const uint32_t* pb = gBb + (it) * 16; \
        CP16(d0,          pa); CP16(d0 + 16,          pa + 4); \
        CP16(d0 + 8192,   ps); CP16(d0 + 8192 + 16,   ps + 4); \
        CP16(d0 + 16384,  pb); CP16(d0 + 16384 + 16,  pb + 4); \
        if (TERM3) { \
            const uint32_t* pq = gBs + (it) * 16; \
            CP16(d0 + 24576,  pq); CP16(d0 + 24576 + 16,  pq + 4); \
        } \
        CP_COMMIT(); \
    } while (0)

    float acc[4][4][4];
#pragma unroll
    for (int mt = 0; mt < 4; mt++)
#pragma unroll
        for (int nt = 0; nt < 4; nt++)
#pragma unroll
            for (int c = 0; c < 4; c++) acc[mt][nt][c] = 0.f;

    const int nIter = K2 >> 4;
    STAGE(0, 0);
    STAGE(1, 1);

    int buf = 0;
    for (int it = 0; it < nIter; it++) {
        if (it + 1 < nIter) { CP_WAIT1(); } else { CP_WAIT0(); }
        __syncthreads();
        if (it + 2 < nIter) {
            int nb = buf + 2; if (nb >= 3) nb -= 3;
            STAGE(it + 2, nb);
        }
        const uint32_t* sA = sm + buf * 8192;
        const uint32_t* sB = sA + 4096;

        uint4 bb[4], bs[4];
#pragma unroll
        for (int nt = 0; nt < 4; nt++) {
            const uint32_t* p = sB + (warp_n * 32 + nt * 8 + rw) * 16 + 4 * q;
            bb[nt] = *(const uint4*)p;
            if (TERM3) bs[nt] = *(const uint4*)(p + 2048);
        }
#pragma unroll
        for (int mt = 0; mt < 4; mt++) {
            const uint32_t* p = sA + (warp_m * 64 + mt * 16 + rw) * 16 + 4 * q;
            uint4 alo = *(const uint4*)p;
            uint4 ahi = *(const uint4*)(p + 128);
            uint4 slo = *(const uint4*)(p + 2048);
            uint4 shi = *(const uint4*)(p + 2048 + 128);
            // term 1: Ab*Bb (ks0, ks1)
#pragma unroll
            for (int nt = 0; nt < 4; nt++)
                mma_h(acc[mt][nt], alo.x, ahi.x, alo.y, ahi.y, bb[nt].x, bb[nt].y);
#pragma unroll
            for (int nt = 0; nt < 4; nt++)
                mma_h(acc[mt][nt], alo.z, ahi.z, alo.w, ahi.w, bb[nt].z, bb[nt].w);
            // term 2: As*Bb
#pragma unroll
            for (int nt = 0; nt < 4; nt++)
                mma_h(acc[mt][nt], slo.x, shi.x, slo.y, shi.y, bb[nt].x, bb[nt].y);
#pragma unroll
            for (int nt = 0; nt < 4; nt++)
                mma_h(acc[mt][nt], slo.z, shi.z, slo.w, shi.w, bb[nt].z, bb[nt].w);
            // term 3 (optional): Ab*Bs
            if (TERM3) {
#pragma unroll
                for (int nt = 0; nt < 4; nt++)
                    mma_h(acc[mt][nt], alo.x, ahi.x, alo.y, ahi.y, bs[nt].x, bs[nt].y);
#pragma unroll
                for (int nt = 0; nt < 4; nt++)
                    mma_h(acc[mt][nt], alo.z, ahi.z, alo.w, ahi.w, bs[nt].z, bs[nt].w);
            }
        }
        buf++; if (buf >= 3) buf -= 3;
    }

    // ---- epilogue ----
#pragma unroll
    for (int mt = 0; mt < 4; mt++) {
#pragma unroll
        for (int nt = 0; nt < 4; nt++) {
            int row = rowBase + warp_m * 64 + mt * 16 + rw;
            int col = colBase + warp_n * 32 + nt * 8 + q * 2;
            float b0 = bias[col], b1 = bias[col + 1];
            float v0 = acc[mt][nt][0] + b0, v1 = acc[mt][nt][1] + b1;
            float v2 = acc[mt][nt][2] + b0, v3 = acc[mt][nt][3] + b1;
            if (EPI == 1) {
                v0 = tanhf(v0); v1 = tanhf(v1); v2 = tanhf(v2); v3 = tanhf(v3);
                int dcol = gidx(col >> 1);
                uint32_t bbv, ssv;
                split2h(v0, v1, bbv, ssv);
                Hb[(size_t)row * (M >> 1) + dcol] = bbv;
                Hs[(size_t)row * (M >> 1) + dcol] = ssv;
                split2h(v2, v3, bbv, ssv);
                Hb[(size_t)(row + 8) * (M >> 1) + dcol] = bbv;
                Hs[(size_t)(row + 8) * (M >> 1) + dcol] = ssv;
            } else {
                *(float2*)&C[(size_t)row * M + col]       = make_float2(v0, v1);
                *(float2*)&C[(size_t)(row + 8) * M + col] = make_float2(v2, v3);
            }
        }
    }
#undef STAGE
}

// ======================= spline =======================
__device__ __forceinline__ float softplusf(float x) {
    return (x > 20.0f) ? x : log1pf(expf(x));
}

__global__ void __launch_bounds__(128) spline_kernel(
    const float* __restrict__ xin, int xoff,
    const float* __restrict__ params,
    float* __restrict__ z, int zoff,
    float* __restrict__ logdet, int add)
{
    const int n = blockIdx.x;
    const int d = threadIdx.x;

    __shared__ float ps[1792];
    {
        const float4* src = (const float4*)(params + (size_t)n * 1792);
#pragma unroll
        for (int i = 0; i < 3; i++)
            *(float4*)&ps[(d + i * 128) * 4] = src[d + i * 128];
        if (d < 64) *(float4*)&ps[(d + 384) * 4] = src[d + 384];
    }
    __syncthreads();

    float raw[14];
#pragma unroll
    for (int j = 0; j < 14; j++) raw[j] = ps[d * 14 + j];

    const float t = xin[(size_t)n * 256 + xoff + d];

    float cw[6], wd[5];
    {
        float m = raw[0];
#pragma unroll
        for (int j = 1; j < 5; j++) m = fmaxf(m, raw[j]);
        float e[5], s = 0.f;
#pragma unroll
        for (int j = 0; j < 5; j++) { e[j] = expf(raw[j] - m); s += e[j]; }
        float Wu[5];
#pragma unroll
        for (int j = 0; j < 5; j++) Wu[j] = 2.0f * BVAL * e[j] / s;
        float m2 = Wu[0];
#pragma unroll
        for (int j = 1; j < 5; j++) m2 = fmaxf(m2, Wu[j]);
        float e2[5], s2 = 0.f;
#pragma unroll
        for (int j = 0; j < 5; j++) { e2[j] = expf(Wu[j] - m2); s2 += e2[j]; }
        cw[0] = -BVAL;
        float run = 0.f;
#pragma unroll
        for (int j = 0; j < 5; j++) {
            float w = MIN_BW + (1.0f - MIN_BW * KBINS) * (e2[j] / s2);
            run += w;
            cw[j + 1] = 2.0f * BVAL * run - BVAL;
        }
        cw[5] = BVAL;
#pragma unroll
        for (int j = 0; j < 5; j++) wd[j] = cw[j + 1] - cw[j];
    }

    float ch[6], hd[5];
    {
        float m = raw[5];
#pragma unroll
        for (int j = 1; j < 5; j++) m = fmaxf(m, raw[5 + j]);
        float e[5], s = 0.f;
#pragma unroll
        for (int j = 0; j < 5; j++) { e[j] = expf(raw[5 + j] - m); s += e[j]; }
        float Hu[5];
#pragma unroll
        for (int j = 0; j < 5; j++) Hu[j] = 2.0f * BVAL * e[j] / s;
        float m2 = Hu[0];
#pragma unroll
        for (int j = 1; j < 5; j++) m2 = fmaxf(m2, Hu[j]);
        float e2[5], s2 = 0.f;
#pragma unroll
        for (int j = 0; j < 5; j++) { e2[j] = expf(Hu[j] - m2); s2 += e2[j]; }
        ch[0] = -BVAL;
        float run = 0.f;
#pragma unroll
        for (int j = 0; j < 5; j++) {
            float h = MIN_BH + (1.0f - MIN_BH * KBINS) * (e2[j] / s2);
            run += h;
            ch[j + 1] = 2.0f * BVAL * run - BVAL;
        }
        ch[5] = BVAL;
#pragma unroll
        for (int j = 0; j < 5; j++) hd[j] = ch[j + 1] - ch[j];
    }

    float deriv[6];
    deriv[0] = 1.0f;
    deriv[5] = 1.0f;
#pragma unroll
    for (int j = 0; j < 4; j++) {
        float du = softplusf(raw[10 + j]);
        deriv[j + 1] = MIN_DV + softplusf(du);
    }

    const float xc = fminf(fmaxf(t, -BVAL), BVAL);
    int cnt = 0;
#pragma unroll
    for (int j = 0; j < 6; j++) cnt += (xc >= cw[j]) ? 1 : 0;
    int idx = min(max(cnt - 1, 0), 4);

    const float icw = cw[idx], iw = wd[idx];
    const float ich = ch[idx], ih = hd[idx];
    const float delta = ih / iw;
    const float dk = deriv[idx], dk1 = deriv[idx + 1];
    const float theta = (xc - icw) / iw;
    const float t1m = theta * (1.0f - theta);
    const float num = ih * (delta * theta * theta + dk * t1m);
    const float den = delta + (dk + dk1 - 2.0f * delta) * t1m;
    const float y = ich + num / den;
    const float omt = 1.0f - theta;
    const float dnum = delta * delta * (dk1 * theta * theta + 2.0f * delta * t1m + dk * omt * omt);
    const float ld = logf(dnum) - 2.0f * logf(den);

    const bool inside = (t >= -BVAL) && (t <= BVAL);
    const float outv = inside ? y : t;
    const float ldv  = inside ? ld : 0.0f;

    z[(size_t)n * 256 + zoff + d] = outv;

    __shared__ float red[128];
    red[d] = ldv;
    __syncthreads();
#pragma unroll
    for (int s = 64; s > 0; s >>= 1) {
        if (d < s) red[d] += red[d + s];
        __syncthreads();
    }
    if (d == 0) {
        if (add) logdet[n] += red[0];
        else     logdet[n]  = red[0];
    }
}

// ======================= host side =======================
extern "C" void kernel_launch(void* const* d_in, const int* in_sizes, int n_in,
                              void* d_out, int out_size)
{
    const float* x     = (const float*)d_in[0];
    const float* f0_w0 = (const float*)d_in[1];
    const float* f0_b0 = (const float*)d_in[2];
    const float* f0_w1 = (const float*)d_in[3];
    const float* f0_b1 = (const float*)d_in[4];
    const float* f1_w0 = (const float*)d_in[5];
    const float* f1_b0 = (const float*)d_in[6];
    const float* f1_w1 = (const float*)d_in[7];
    const float* f1_b1 = (const float*)d_in[8];

    const int N = in_sizes[0] / 256;              // 32768
    float* z      = (float*)d_out;
    float* logdet = z + (size_t)N * 256;

    uint32_t *xsb, *xss, *hb, *hs, *w0b, *w0s, *w1b, *w1s;
    float* params;
    cudaGetSymbolAddress((void**)&xsb, g_xs_big);
    cudaGetSymbolAddress((void**)&xss, g_xs_sml);
    cudaGetSymbolAddress((void**)&hb,  g_h_big);
    cudaGetSymbolAddress((void**)&hs,  g_h_sml);
    cudaGetSymbolAddress((void**)&params, g_params);
    cudaGetSymbolAddress((void**)&w0b, g_w0b);
    cudaGetSymbolAddress((void**)&w0s, g_w0s);
    cudaGetSymbolAddress((void**)&w1b, g_w1b);
    cudaGetSymbolAddress((void**)&w1s, g_w1s);

    cudaFuncSetAttribute((const void*)gemm_h3<0,0>, cudaFuncAttributeMaxDynamicSharedMemorySize, GEMM_SMEM);
    cudaFuncSetAttribute((const void*)gemm_h3<1,1>, cudaFuncAttributeMaxDynamicSharedMemorySize, GEMM_SMEM);

    const dim3 g1(512 / 128, N / 128);    // (4, 256)
    const dim3 g2(1792 / 128, N / 128);   // (14, 256)
    const int nConvBlocks = N * 64 / 256; // 8192

    // ---- coupling 1 (launch #4 = big GEMM, targeted by ncu capture) ----
    conv_all<<<480 + nConvBlocks, 256>>>(x, 0, f0_w0, f0_w1,
                                         w0b, w0s, w1b, w1s, xsb, xss);          // 1
    gemm_h3<1,1><<<g1, 256, GEMM_SMEM>>>(xsb, xss, w0b, w0s, f0_b0,
                                         nullptr, hb, hs, 512, 64);              // 2
    conv_all<<<480, 256>>>(x, 0, f1_w0, f1_w1,
                           w0b + 512 * 64, w0s + 512 * 64,
                           w1b + 1792 * 256, w1s + 1792 * 256, xsb, xss);        // 3 (weights only)
    gemm_h3<0,0><<<g2, 256, GEMM_SMEM>>>(hb, hs, w1b, w1s, f0_b1,
                                         params, nullptr, nullptr, 1792, 256);   // 4 <- profiled
    spline_kernel<<<N, 128>>>(x, 128, params, z, 128, logdet, 0);                // 5

    // ---- coupling 2 ----
    conv_x<<<nConvBlocks, 256>>>(z, 128, xsb, xss);                              // 6
    gemm_h3<1,1><<<g1, 256, GEMM_SMEM>>>(xsb, xss, w0b + 512 * 64, w0s + 512 * 64,
                                         f1_b0, nullptr, hb, hs, 512, 64);       // 7
    gemm_h3<0,0><<<g2, 256, GEMM_SMEM>>>(hb, hs, w1b + 1792 * 256, w1s + 1792 * 256,
                                         f1_b1, params, nullptr, nullptr, 1792, 256); // 8
    spline_kernel<<<N, 128>>>(x, 0, params, z, 0, logdet, 1);                    // 9
}

// round 13
// speedup vs baseline: 1.6583x; 1.0701x over previous
#include <cuda_runtime.h>
#include <cuda_fp16.h>
#include <math.h>
#include <stdint.h>

// ---------------- scratch (allocation-free: __device__ globals) ----------------
__device__ __align__(1024) uint32_t g_xs_big[32768ULL * 64];
__device__ __align__(1024) uint32_t g_xs_sml[32768ULL * 64];
__device__ __align__(1024) uint32_t g_h_big[32768ULL * 256];
__device__ __align__(1024) uint32_t g_h_sml[32768ULL * 256];
__device__ __align__(1024) float    g_params[32768ULL * 1792];
__device__ __align__(1024) uint32_t g_w0b[2][512 * 64];
__device__ __align__(1024) uint32_t g_w0s[2][512 * 64];
__device__ __align__(1024) uint32_t g_w1b[2][1792 * 256];
__device__ __align__(1024) uint32_t g_w1s[2][1792 * 256];

#define BVAL   3.0f
#define KBINS  5
#define MIN_BW 0.001f
#define MIN_BH 0.001f
#define MIN_DV 0.001f

// ======================= helpers =======================
__device__ __forceinline__ int gidx(int kpg) {
    return (kpg & ~15) | ((kpg & 3) << 2) | ((kpg >> 2) & 3);
}

__device__ __forceinline__ void split2h(float x0, float x1, uint32_t& b, uint32_t& s) {
    __half b0 = __float2half_rn(x0);
    __half b1 = __float2half_rn(x1);
    float r0 = x0 - __half2float(b0);
    float r1 = x1 - __half2float(b1);
    __half s0 = __float2half_rn(r0);
    __half s1 = __float2half_rn(r1);
    b = (uint32_t)__half_as_ushort(b0) | ((uint32_t)__half_as_ushort(b1) << 16);
    s = (uint32_t)__half_as_ushort(s0) | ((uint32_t)__half_as_ushort(s1) << 16);
}

__device__ __forceinline__ void mma_h(float* d,
                                      uint32_t a0, uint32_t a1, uint32_t a2, uint32_t a3,
                                      uint32_t b0, uint32_t b1) {
    asm volatile(
        "mma.sync.aligned.m16n8k16.row.col.f32.f16.f16.f32 "
        "{%0,%1,%2,%3}, {%4,%5,%6,%7}, {%8,%9}, {%0,%1,%2,%3};"
        : "+f"(d[0]), "+f"(d[1]), "+f"(d[2]), "+f"(d[3])
        : "r"(a0), "r"(a1), "r"(a2), "r"(a3), "r"(b0), "r"(b1));
}

#define CP16(dst, src) \
    asm volatile("cp.async.cg.shared.global [%0], [%1], 16;" :: "r"(dst), "l"(src) : "memory")
#define CP_COMMIT() asm volatile("cp.async.commit_group;" ::: "memory")
#define CP_WAIT1()  asm volatile("cp.async.wait_group 1;" ::: "memory")
#define CP_WAIT0()  asm volatile("cp.async.wait_group 0;" ::: "memory")

__device__ __forceinline__ uint32_t smem_u32(const void* p) {
    uint32_t a;
    asm("{ .reg .u64 t; cvta.to.shared.u64 t, %1; cvt.u32.u64 %0, t; }" : "=r"(a) : "l"(p));
    return a;
}

// fast transcendentals (fast-math-safe regardless of compiler flags)
__device__ __forceinline__ float fexpf(float x) { return __expf(x); }
__device__ __forceinline__ float flogf(float x) { return __logf(x); }
__device__ __forceinline__ float fsoftplus(float x) {
    return (x > 20.0f) ? x : __logf(1.0f + __expf(x));
}

// ======================= converters =======================
__device__ __forceinline__ void conv_w_body(
    const float* __restrict__ w, int M, int K2, int m0, int kp0,
    uint32_t* __restrict__ ob, uint32_t* __restrict__ os,
    uint32_t (*tb)[33], uint32_t (*ts)[33], int tid)
{
    const int xx = tid & 31, yy = tid >> 5;
    for (int i = yy; i < 32; i += 8) {
        int kpg = kp0 + i, m = m0 + xx;
        float v0 = w[(size_t)(2 * kpg) * M + m];
        float v1 = w[(size_t)(2 * kpg + 1) * M + m];
        split2h(v0, v1, tb[i][xx], ts[i][xx]);
    }
    __syncthreads();
    for (int i = yy; i < 32; i += 8) {
        int m = m0 + i;
        size_t dst = (size_t)m * K2 + gidx(kp0 + xx);
        ob[dst] = tb[xx][i]; os[dst] = ts[xx][i];
    }
}

__global__ void __launch_bounds__(256) conv_all(
    const float* __restrict__ x, int xoff,
    const float* __restrict__ w0, const float* __restrict__ w1,
    uint32_t* __restrict__ w0bD, uint32_t* __restrict__ w0sD,
    uint32_t* __restrict__ w1bD, uint32_t* __restrict__ w1sD,
    uint32_t* __restrict__ xb, uint32_t* __restrict__ xs)
{
    __shared__ uint32_t tb[32][33], ts[32][33];
    const int bid = blockIdx.x;
    const int tid = threadIdx.x;
    if (bid < 32) {
        conv_w_body(w0, 512, 64, (bid & 15) * 32, (bid >> 4) * 32, w0bD, w0sD, tb, ts, tid);
    } else if (bid < 480) {
        int b = bid - 32;
        conv_w_body(w1, 1792, 256, (b % 56) * 32, (b / 56) * 32, w1bD, w1sD, tb, ts, tid);
    } else {
        int t = (bid - 480) * 256 + tid;
        int row = t >> 6, kpg = t & 63;
        float2 v = *(const float2*)(x + (size_t)row * 256 + xoff + 2 * kpg);
        uint32_t b_, s_;
        split2h(v.x, v.y, b_, s_);
        int dst = row * 64 + gidx(kpg);
        xb[dst] = b_; xs[dst] = s_;
    }
}

// ======================= fp16 split tensor-core GEMM =======================
// Block 128x128 (BK=16 words=32k), 256 threads (8 warps 2x4), warp 64x32.
// TERM3=1: full 3-term (Ab*Bb + As*Bb + Ab*Bs)  — GEMM1 (accuracy).
// TERM3=0: 2-term   (Ab*Bb + As*Bb)             — GEMM2 (speed).
#define GEMM_SMEM (3 * 32768)

template <int EPI, int TERM3>
__global__ void __launch_bounds__(256, 2) gemm_h3(
    const uint32_t* __restrict__ Ab, const uint32_t* __restrict__ As,
    const uint32_t* __restrict__ Bb, const uint32_t* __restrict__ Bs,
    const float* __restrict__ bias,
    float* __restrict__ C, uint32_t* __restrict__ Hb, uint32_t* __restrict__ Hs,
    int M, int K2)
{
    extern __shared__ uint32_t sm[];
    const uint32_t sbase = smem_u32(sm);
    const int tid  = threadIdx.x;
    const int lane = tid & 31;
    const int wid  = tid >> 5;
    const int warp_m = wid & 1;
    const int warp_n = wid >> 1;
    const int rowBase = blockIdx.y * 128;
    const int colBase = blockIdx.x * 128;
    const int q  = lane & 3;
    const int rw = lane >> 2;

    const int cr  = tid >> 1;
    const int cw8 = (tid & 1) * 8;
    const uint32_t* gAb = Ab + (size_t)(rowBase + cr) * K2 + cw8;
    const uint32_t* gAs = As + (size_t)(rowBase + cr) * K2 + cw8;
    const uint32_t* gBb = Bb + (size_t)(colBase + cr) * K2 + cw8;
    const uint32_t* gBs = Bs + (size_t)(colBase + cr) * K2 + cw8;
    const uint32_t sdst = sbase + (uint32_t)(cr * 16 + cw8) * 4;

#define STAGE(it, buf) do { \
        uint32_t d0 = sdst + (uint32_t)(buf) * 32768u; \
        const uint32_t* pa = gAb + (it) * 16; \
        const uint32_t* ps = gAs + (it) * 16; \
        const uint32_t* pb = gBb + (it) * 16; \
        CP16(d0,          pa); CP16(d0 + 16,          pa + 4); \
        CP16(d0 + 8192,   ps); CP16(d0 + 8192 + 16,   ps + 4); \
        CP16(d0 + 16384,  pb); CP16(d0 + 16384 + 16,  pb + 4); \
        if (TERM3) { \
            const uint32_t* pq = gBs + (it) * 16; \
            CP16(d0 + 24576,  pq); CP16(d0 + 24576 + 16,  pq + 4); \
        } \
        CP_COMMIT(); \
    } while (0)

    float acc[4][4][4];
#pragma unroll
    for (int mt = 0; mt < 4; mt++)
#pragma unroll
        for (int nt = 0; nt < 4; nt++)
#pragma unroll
            for (int c = 0; c < 4; c++) acc[mt][nt][c] = 0.f;

    const int nIter = K2 >> 4;
    STAGE(0, 0);
    STAGE(1, 1);

    int buf = 0;
    for (int it = 0; it < nIter; it++) {
        if (it + 1 < nIter) { CP_WAIT1(); } else { CP_WAIT0(); }
        __syncthreads();
        if (it + 2 < nIter) {
            int nb = buf + 2; if (nb >= 3) nb -= 3;
            STAGE(it + 2, nb);
        }
        const uint32_t* sA = sm + buf * 8192;
        const uint32_t* sB = sA + 4096;

        uint4 bb[4], bs[4];
#pragma unroll
        for (int nt = 0; nt < 4; nt++) {
            const uint32_t* p = sB + (warp_n * 32 + nt * 8 + rw) * 16 + 4 * q;
            bb[nt] = *(const uint4*)p;
            if (TERM3) bs[nt] = *(const uint4*)(p + 2048);
        }
#pragma unroll
        for (int mt = 0; mt < 4; mt++) {
            const uint32_t* p = sA + (warp_m * 64 + mt * 16 + rw) * 16 + 4 * q;
            uint4 alo = *(const uint4*)p;
            uint4 ahi = *(const uint4*)(p + 128);
            uint4 slo = *(const uint4*)(p + 2048);
            uint4 shi = *(const uint4*)(p + 2048 + 128);
#pragma unroll
            for (int nt = 0; nt < 4; nt++)
                mma_h(acc[mt][nt], alo.x, ahi.x, alo.y, ahi.y, bb[nt].x, bb[nt].y);
#pragma unroll
            for (int nt = 0; nt < 4; nt++)
                mma_h(acc[mt][nt], alo.z, ahi.z, alo.w, ahi.w, bb[nt].z, bb[nt].w);
#pragma unroll
            for (int nt = 0; nt < 4; nt++)
                mma_h(acc[mt][nt], slo.x, shi.x, slo.y, shi.y, bb[nt].x, bb[nt].y);
#pragma unroll
            for (int nt = 0; nt < 4; nt++)
                mma_h(acc[mt][nt], slo.z, shi.z, slo.w, shi.w, bb[nt].z, bb[nt].w);
            if (TERM3) {
#pragma unroll
                for (int nt = 0; nt < 4; nt++)
                    mma_h(acc[mt][nt], alo.x, ahi.x, alo.y, ahi.y, bs[nt].x, bs[nt].y);
#pragma unroll
                for (int nt = 0; nt < 4; nt++)
                    mma_h(acc[mt][nt], alo.z, ahi.z, alo.w, ahi.w, bs[nt].z, bs[nt].w);
            }
        }
        buf++; if (buf >= 3) buf -= 3;
    }

    // ---- epilogue ----
#pragma unroll
    for (int mt = 0; mt < 4; mt++) {
#pragma unroll
        for (int nt = 0; nt < 4; nt++) {
            int row = rowBase + warp_m * 64 + mt * 16 + rw;
            int col = colBase + warp_n * 32 + nt * 8 + q * 2;
            float b0 = bias[col], b1 = bias[col + 1];
            float v0 = acc[mt][nt][0] + b0, v1 = acc[mt][nt][1] + b1;
            float v2 = acc[mt][nt][2] + b0, v3 = acc[mt][nt][3] + b1;
            if (EPI == 1) {
                v0 = tanhf(v0); v1 = tanhf(v1); v2 = tanhf(v2); v3 = tanhf(v3);
                int dcol = gidx(col >> 1);
                uint32_t bbv, ssv;
                split2h(v0, v1, bbv, ssv);
                Hb[(size_t)row * (M >> 1) + dcol] = bbv;
                Hs[(size_t)row * (M >> 1) + dcol] = ssv;
                split2h(v2, v3, bbv, ssv);
                Hb[(size_t)(row + 8) * (M >> 1) + dcol] = bbv;
                Hs[(size_t)(row + 8) * (M >> 1) + dcol] = ssv;
            } else {
                *(float2*)&C[(size_t)row * M + col]       = make_float2(v0, v1);
                *(float2*)&C[(size_t)(row + 8) * M + col] = make_float2(v2, v3);
            }
        }
    }
#undef STAGE
}

// ======================= spline =======================
// If zb != nullptr, also emits the fp16-split pair-packed form of the output
// (feeds coupling-2 GEMM1 directly; replaces the conv_x launch).
__global__ void __launch_bounds__(128) spline_kernel(
    const float* __restrict__ xin, int xoff,
    const float* __restrict__ params,
    float* __restrict__ z, int zoff,
    float* __restrict__ logdet, int add,
    uint32_t* __restrict__ zb, uint32_t* __restrict__ zs)
{
    const int n = blockIdx.x;
    const int d = threadIdx.x;

    __shared__ float ps[1792];
    {
        const float4* src = (const float4*)(params + (size_t)n * 1792);
#pragma unroll
        for (int i = 0; i < 3; i++)
            *(float4*)&ps[(d + i * 128) * 4] = src[d + i * 128];
        if (d < 64) *(float4*)&ps[(d + 384) * 4] = src[d + 384];
    }
    __syncthreads();

    float raw[14];
#pragma unroll
    for (int j = 0; j < 14; j++) raw[j] = ps[d * 14 + j];

    const float t = xin[(size_t)n * 256 + xoff + d];

    float cw[6], wd[5];
    {
        float m = raw[0];
#pragma unroll
        for (int j = 1; j < 5; j++) m = fmaxf(m, raw[j]);
        float e[5], s = 0.f;
#pragma unroll
        for (int j = 0; j < 5; j++) { e[j] = fexpf(raw[j] - m); s += e[j]; }
        float inv = 1.0f / s;
        float Wu[5];
#pragma unroll
        for (int j = 0; j < 5; j++) Wu[j] = 2.0f * BVAL * e[j] * inv;
        float m2 = Wu[0];
#pragma unroll
        for (int j = 1; j < 5; j++) m2 = fmaxf(m2, Wu[j]);
        float e2[5], s2 = 0.f;
#pragma unroll
        for (int j = 0; j < 5; j++) { e2[j] = fexpf(Wu[j] - m2); s2 += e2[j]; }
        float inv2 = 1.0f / s2;
        cw[0] = -BVAL;
        float run = 0.f;
#pragma unroll
        for (int j = 0; j < 5; j++) {
            float w = MIN_BW + (1.0f - MIN_BW * KBINS) * (e2[j] * inv2);
            run += w;
            cw[j + 1] = 2.0f * BVAL * run - BVAL;
        }
        cw[5] = BVAL;
#pragma unroll
        for (int j = 0; j < 5; j++) wd[j] = cw[j + 1] - cw[j];
    }

    float ch[6], hd[5];
    {
        float m = raw[5];
#pragma unroll
        for (int j = 1; j < 5; j++) m = fmaxf(m, raw[5 + j]);
        float e[5], s = 0.f;
#pragma unroll
        for (int j = 0; j < 5; j++) { e[j] = fexpf(raw[5 + j] - m); s += e[j]; }
        float inv = 1.0f / s;
        float Hu[5];
#pragma unroll
        for (int j = 0; j < 5; j++) Hu[j] = 2.0f * BVAL * e[j] * inv;
        float m2 = Hu[0];
#pragma unroll
        for (int j = 1; j < 5; j++) m2 = fmaxf(m2, Hu[j]);
        float e2[5], s2 = 0.f;
#pragma unroll
        for (int j = 0; j < 5; j++) { e2[j] = fexpf(Hu[j] - m2); s2 += e2[j]; }
        float inv2 = 1.0f / s2;
        ch[0] = -BVAL;
        float run = 0.f;
#pragma unroll
        for (int j = 0; j < 5; j++) {
            float h = MIN_BH + (1.0f - MIN_BH * KBINS) * (e2[j] * inv2);
            run += h;
            ch[j + 1] = 2.0f * BVAL * run - BVAL;
        }
        ch[5] = BVAL;
#pragma unroll
        for (int j = 0; j < 5; j++) hd[j] = ch[j + 1] - ch[j];
    }

    float deriv[6];
    deriv[0] = 1.0f;
    deriv[5] = 1.0f;
#pragma unroll
    for (int j = 0; j < 4; j++) {
        float du = fsoftplus(raw[10 + j]);
        deriv[j + 1] = MIN_DV + fsoftplus(du);
    }

    const float xc = fminf(fmaxf(t, -BVAL), BVAL);
    int cnt = 0;
#pragma unroll
    for (int j = 0; j < 6; j++) cnt += (xc >= cw[j]) ? 1 : 0;
    int idx = min(max(cnt - 1, 0), 4);

    const float icw = cw[idx], iw = wd[idx];
    const float ich = ch[idx], ih = hd[idx];
    const float delta = ih / iw;
    const float dk = deriv[idx], dk1 = deriv[idx + 1];
    const float theta = (xc - icw) / iw;
    const float t1m = theta * (1.0f - theta);
    const float num = ih * (delta * theta * theta + dk * t1m);
    const float den = delta + (dk + dk1 - 2.0f * delta) * t1m;
    const float y = ich + num / den;
    const float omt = 1.0f - theta;
    const float dnum = delta * delta * (dk1 * theta * theta + 2.0f * delta * t1m + dk * omt * omt);
    const float ld = flogf(dnum) - 2.0f * flogf(den);

    const bool inside = (t >= -BVAL) && (t <= BVAL);
    const float outv = inside ? y : t;
    const float ldv  = inside ? ld : 0.0f;

    z[(size_t)n * 256 + zoff + d] = outv;

    // optional: emit fp16-split pair-packed output for the next coupling's GEMM
    if (zb != nullptr) {
        float nb = __shfl_down_sync(0xffffffffu, outv, 1);
        if ((d & 1) == 0) {
            uint32_t bbv, ssv;
            split2h(outv, nb, bbv, ssv);
            int dst = n * 64 + gidx(d >> 1);
            zb[dst] = bbv;
            zs[dst] = ssv;
        }
    }

    __shared__ float red[128];
    red[d] = ldv;
    __syncthreads();
#pragma unroll
    for (int s = 64; s > 0; s >>= 1) {
        if (d < s) red[d] += red[d + s];
        __syncthreads();
    }
    if (d == 0) {
        if (add) logdet[n] += red[0];
        else     logdet[n]  = red[0];
    }
}

// ======================= host side =======================
extern "C" void kernel_launch(void* const* d_in, const int* in_sizes, int n_in,
                              void* d_out, int out_size)
{
    const float* x     = (const float*)d_in[0];
    const float* f0_w0 = (const float*)d_in[1];
    const float* f0_b0 = (const float*)d_in[2];
    const float* f0_w1 = (const float*)d_in[3];
    const float* f0_b1 = (const float*)d_in[4];
    const float* f1_w0 = (const float*)d_in[5];
    const float* f1_b0 = (const float*)d_in[6];
    const float* f1_w1 = (const float*)d_in[7];
    const float* f1_b1 = (const float*)d_in[8];

    const int N = in_sizes[0] / 256;              // 32768
    float* z      = (float*)d_out;
    float* logdet = z + (size_t)N * 256;

    uint32_t *xsb, *xss, *hb, *hs, *w0b, *w0s, *w1b, *w1s;
    float* params;
    cudaGetSymbolAddress((void**)&xsb, g_xs_big);
    cudaGetSymbolAddress((void**)&xss, g_xs_sml);
    cudaGetSymbolAddress((void**)&hb,  g_h_big);
    cudaGetSymbolAddress((void**)&hs,  g_h_sml);
    cudaGetSymbolAddress((void**)&params, g_params);
    cudaGetSymbolAddress((void**)&w0b, g_w0b);
    cudaGetSymbolAddress((void**)&w0s, g_w0s);
    cudaGetSymbolAddress((void**)&w1b, g_w1b);
    cudaGetSymbolAddress((void**)&w1s, g_w1s);

    cudaFuncSetAttribute((const void*)gemm_h3<0,0>, cudaFuncAttributeMaxDynamicSharedMemorySize, GEMM_SMEM);
    cudaFuncSetAttribute((const void*)gemm_h3<1,1>, cudaFuncAttributeMaxDynamicSharedMemorySize, GEMM_SMEM);

    const dim3 g1(512 / 128, N / 128);    // (4, 256)
    const dim3 g2(1792 / 128, N / 128);   // (14, 256)
    const int nConvBlocks = N * 64 / 256; // 8192

    // ---- coupling 1 (launch #4 = big GEMM, targeted by ncu capture) ----
    conv_all<<<480 + nConvBlocks, 256>>>(x, 0, f0_w0, f0_w1,
                                         w0b, w0s, w1b, w1s, xsb, xss);          // 1
    gemm_h3<1,1><<<g1, 256, GEMM_SMEM>>>(xsb, xss, w0b, w0s, f0_b0,
                                         nullptr, hb, hs, 512, 64);              // 2
    conv_all<<<480, 256>>>(x, 0, f1_w0, f1_w1,
                           w0b + 512 * 64, w0s + 512 * 64,
                           w1b + 1792 * 256, w1s + 1792 * 256, xsb, xss);        // 3 (weights only)
    gemm_h3<0,0><<<g2, 256, GEMM_SMEM>>>(hb, hs, w1b, w1s, f0_b1,
                                         params, nullptr, nullptr, 1792, 256);   // 4 <- profiled
    spline_kernel<<<N, 128>>>(x, 128, params, z, 128, logdet, 0, xsb, xss);      // 5 (also emits split z1)

    // ---- coupling 2 ----
    gemm_h3<1,1><<<g1, 256, GEMM_SMEM>>>(xsb, xss, w0b + 512 * 64, w0s + 512 * 64,
                                         f1_b0, nullptr, hb, hs, 512, 64);       // 6
    gemm_h3<0,0><<<g2, 256, GEMM_SMEM>>>(hb, hs, w1b + 1792 * 256, w1s + 1792 * 256,
                                         f1_b1, params, nullptr, nullptr, 1792, 256); // 7
    spline_kernel<<<N, 128>>>(x, 0, params, z, 0, logdet, 1, nullptr, nullptr);  // 8
}

// round 14
// speedup vs baseline: 1.7168x; 1.0352x over previous
#include <cuda_runtime.h>
#include <cuda_fp16.h>
#include <math.h>
#include <stdint.h>

// ---------------- scratch (allocation-free: __device__ globals) ----------------
__device__ __align__(1024) uint32_t g_xs_big[32768ULL * 64];
__device__ __align__(1024) uint32_t g_xs_sml[32768ULL * 64];
__device__ __align__(1024) uint32_t g_h_big[32768ULL * 256];
__device__ __align__(1024) uint32_t g_h_sml[32768ULL * 256];
__device__ __align__(1024) float    g_params[32768ULL * 1792];
__device__ __align__(1024) uint32_t g_w0b[2][512 * 64];
__device__ __align__(1024) uint32_t g_w0s[2][512 * 64];
__device__ __align__(1024) uint32_t g_w1b[2][1792 * 256];
__device__ __align__(1024) uint32_t g_w1s[2][1792 * 256];

#define BVAL   3.0f
#define KBINS  5
#define MIN_BW 0.001f
#define MIN_BH 0.001f
#define MIN_DV 0.001f

// ======================= helpers =======================
__device__ __forceinline__ int gidx(int kpg) {
    return (kpg & ~15) | ((kpg & 3) << 2) | ((kpg >> 2) & 3);
}

__device__ __forceinline__ void split2h(float x0, float x1, uint32_t& b, uint32_t& s) {
    __half b0 = __float2half_rn(x0);
    __half b1 = __float2half_rn(x1);
    float r0 = x0 - __half2float(b0);
    float r1 = x1 - __half2float(b1);
    __half s0 = __float2half_rn(r0);
    __half s1 = __float2half_rn(r1);
    b = (uint32_t)__half_as_ushort(b0) | ((uint32_t)__half_as_ushort(b1) << 16);
    s = (uint32_t)__half_as_ushort(s0) | ((uint32_t)__half_as_ushort(s1) << 16);
}

__device__ __forceinline__ void mma_h(float* d,
                                      uint32_t a0, uint32_t a1, uint32_t a2, uint32_t a3,
                                      uint32_t b0, uint32_t b1) {
    asm volatile(
        "mma.sync.aligned.m16n8k16.row.col.f32.f16.f16.f32 "
        "{%0,%1,%2,%3}, {%4,%5,%6,%7}, {%8,%9}, {%0,%1,%2,%3};"
        : "+f"(d[0]), "+f"(d[1]), "+f"(d[2]), "+f"(d[3])
        : "r"(a0), "r"(a1), "r"(a2), "r"(a3), "r"(b0), "r"(b1));
}

#define CP16(dst, src) \
    asm volatile("cp.async.cg.shared.global [%0], [%1], 16;" :: "r"(dst), "l"(src) : "memory")
#define CP_COMMIT() asm volatile("cp.async.commit_group;" ::: "memory")
#define CP_WAIT1()  asm volatile("cp.async.wait_group 1;" ::: "memory")
#define CP_WAIT0()  asm volatile("cp.async.wait_group 0;" ::: "memory")

__device__ __forceinline__ uint32_t smem_u32(const void* p) {
    uint32_t a;
    asm("{ .reg .u64 t; cvta.to.shared.u64 t, %1; cvt.u32.u64 %0, t; }" : "=r"(a) : "l"(p));
    return a;
}

__device__ __forceinline__ float fexpf(float x) { return __expf(x); }
__device__ __forceinline__ float flogf(float x) { return __logf(x); }
__device__ __forceinline__ float fsoftplus(float x) {
    return (x > 20.0f) ? x : __logf(1.0f + __expf(x));
}

// ======================= converters =======================
__device__ __forceinline__ void conv_w_body(
    const float* __restrict__ w, int M, int K2, int m0, int kp0,
    uint32_t* __restrict__ ob, uint32_t* __restrict__ os,
    uint32_t (*tb)[33], uint32_t (*ts)[33], int tid)
{
    const int xx = tid & 31, yy = tid >> 5;
    for (int i = yy; i < 32; i += 8) {
        int kpg = kp0 + i, m = m0 + xx;
        float v0 = w[(size_t)(2 * kpg) * M + m];
        float v1 = w[(size_t)(2 * kpg + 1) * M + m];
        split2h(v0, v1, tb[i][xx], ts[i][xx]);
    }
    __syncthreads();
    for (int i = yy; i < 32; i += 8) {
        int m = m0 + i;
        size_t dst = (size_t)m * K2 + gidx(kp0 + xx);
        ob[dst] = tb[xx][i]; os[dst] = ts[xx][i];
    }
}

// One launch: all 4 weight matrices (both couplings) + x conversion.
// blocks [0,32): w0 c0; [32,480): w1 c0; [480,512): w0 c1; [512,960): w1 c1; [960, ...): x.
__global__ void __launch_bounds__(256) conv_all(
    const float* __restrict__ x, int xoff,
    const float* __restrict__ w0a, const float* __restrict__ w1a,
    const float* __restrict__ w0c, const float* __restrict__ w1c,
    uint32_t* __restrict__ w0bD, uint32_t* __restrict__ w0sD,
    uint32_t* __restrict__ w1bD, uint32_t* __restrict__ w1sD,
    uint32_t* __restrict__ xb, uint32_t* __restrict__ xs)
{
    __shared__ uint32_t tb[32][33], ts[32][33];
    const int bid = blockIdx.x;
    const int tid = threadIdx.x;
    if (bid < 32) {
        conv_w_body(w0a, 512, 64, (bid & 15) * 32, (bid >> 4) * 32, w0bD, w0sD, tb, ts, tid);
    } else if (bid < 480) {
        int b = bid - 32;
        conv_w_body(w1a, 1792, 256, (b % 56) * 32, (b / 56) * 32, w1bD, w1sD, tb, ts, tid);
    } else if (bid < 512) {
        int b = bid - 480;
        conv_w_body(w0c, 512, 64, (b & 15) * 32, (b >> 4) * 32,
                    w0bD + 512 * 64, w0sD + 512 * 64, tb, ts, tid);
    } else if (bid < 960) {
        int b = bid - 512;
        conv_w_body(w1c, 1792, 256, (b % 56) * 32, (b / 56) * 32,
                    w1bD + 1792 * 256, w1sD + 1792 * 256, tb, ts, tid);
    } else {
        int t = (bid - 960) * 256 + tid;
        int row = t >> 6, kpg = t & 63;
        float2 v = *(const float2*)(x + (size_t)row * 256 + xoff + 2 * kpg);
        uint32_t b_, s_;
        split2h(v.x, v.y, b_, s_);
        int dst = row * 64 + gidx(kpg);
        xb[dst] = b_; xs[dst] = s_;
    }
}

// ======================= fp16 split tensor-core GEMM =======================
// Block 128x128 (BK=16 words=32k), 256 threads (8 warps 2x4), warp 64x32.
// TERM3=1: 3-term (Ab*Bb + As*Bb + Ab*Bs)  — GEMM1 (accuracy).
// TERM3=0: 2-term (Ab*Bb + As*Bb)          — GEMM2 (speed; at the HMMA floor).
// EPI=1: tanh + split-fp16 via smem-staged coalesced writes to Hb/Hs.
#define GEMM_SMEM (3 * 32768)

template <int EPI, int TERM3>
__global__ void __launch_bounds__(256, 2) gemm_h3(
    const uint32_t* __restrict__ Ab, const uint32_t* __restrict__ As,
    const uint32_t* __restrict__ Bb, const uint32_t* __restrict__ Bs,
    const float* __restrict__ bias,
    float* __restrict__ C, uint32_t* __restrict__ Hb, uint32_t* __restrict__ Hs,
    int M, int K2)
{
    extern __shared__ uint32_t sm[];
    const uint32_t sbase = smem_u32(sm);
    const int tid  = threadIdx.x;
    const int lane = tid & 31;
    const int wid  = tid >> 5;
    const int warp_m = wid & 1;
    const int warp_n = wid >> 1;
    const int rowBase = blockIdx.y * 128;
    const int colBase = blockIdx.x * 128;
    const int q  = lane & 3;
    const int rw = lane >> 2;

    const int cr  = tid >> 1;
    const int cw8 = (tid & 1) * 8;
    const uint32_t* gAb = Ab + (size_t)(rowBase + cr) * K2 + cw8;
    const uint32_t* gAs = As + (size_t)(rowBase + cr) * K2 + cw8;
    const uint32_t* gBb = Bb + (size_t)(colBase + cr) * K2 + cw8;
    const uint32_t* gBs = Bs + (size_t)(colBase + cr) * K2 + cw8;
    const uint32_t sdst = sbase + (uint32_t)(cr * 16 + cw8) * 4;

#define STAGE(it, buf) do { \
        uint32_t d0 = sdst + (uint32_t)(buf) * 32768u; \
        const uint32_t* pa = gAb + (it) * 16; \
        const uint32_t* ps = gAs + (it) * 16; \
        const uint32_t* pb = gBb + (it) * 16; \
        CP16(d0,          pa); CP16(d0 + 16,          pa + 4); \
        CP16(d0 + 8192,   ps); CP16(d0 + 8192 + 16,   ps + 4); \
        CP16(d0 + 16384,  pb); CP16(d0 + 16384 + 16,  pb + 4); \
        if (TERM3) { \
            const uint32_t* pq = gBs + (it) * 16; \
            CP16(d0 + 24576,  pq); CP16(d0 + 24576 + 16,  pq + 4); \
        } \
        CP_COMMIT(); \
    } while (0)

    float acc[4][4][4];
#pragma unroll
    for (int mt = 0; mt < 4; mt++)
#pragma unroll
        for (int nt = 0; nt < 4; nt++)
#pragma unroll
            for (int c = 0; c < 4; c++) acc[mt][nt][c] = 0.f;

    const int nIter = K2 >> 4;
    STAGE(0, 0);
    STAGE(1, 1);

    int buf = 0;
    for (int it = 0; it < nIter; it++) {
        if (it + 1 < nIter) { CP_WAIT1(); } else { CP_WAIT0(); }
        __syncthreads();
        if (it + 2 < nIter) {
            int nb = buf + 2; if (nb >= 3) nb -= 3;
            STAGE(it + 2, nb);
        }
        const uint32_t* sA = sm + buf * 8192;
        const uint32_t* sB = sA + 4096;

        uint4 bb[4], bs[4];
#pragma unroll
        for (int nt = 0; nt < 4; nt++) {
            const uint32_t* p = sB + (warp_n * 32 + nt * 8 + rw) * 16 + 4 * q;
            bb[nt] = *(const uint4*)p;
            if (TERM3) bs[nt] = *(const uint4*)(p + 2048);
        }
#pragma unroll
        for (int mt = 0; mt < 4; mt++) {
            const uint32_t* p = sA + (warp_m * 64 + mt * 16 + rw) * 16 + 4 * q;
            uint4 alo = *(const uint4*)p;
            uint4 ahi = *(const uint4*)(p + 128);
            uint4 slo = *(const uint4*)(p + 2048);
            uint4 shi = *(const uint4*)(p + 2048 + 128);
#pragma unroll
            for (int nt = 0; nt < 4; nt++)
                mma_h(acc[mt][nt], alo.x, ahi.x, alo.y, ahi.y, bb[nt].x, bb[nt].y);
#pragma unroll
            for (int nt = 0; nt < 4; nt++)
                mma_h(acc[mt][nt], alo.z, ahi.z, alo.w, ahi.w, bb[nt].z, bb[nt].w);
#pragma unroll
            for (int nt = 0; nt < 4; nt++)
                mma_h(acc[mt][nt], slo.x, shi.x, slo.y, shi.y, bb[nt].x, bb[nt].y);
#pragma unroll
            for (int nt = 0; nt < 4; nt++)
                mma_h(acc[mt][nt], slo.z, shi.z, slo.w, shi.w, bb[nt].z, bb[nt].w);
            if (TERM3) {
#pragma unroll
                for (int nt = 0; nt < 4; nt++)
                    mma_h(acc[mt][nt], alo.x, ahi.x, alo.y, ahi.y, bs[nt].x, bs[nt].y);
#pragma unroll
                for (int nt = 0; nt < 4; nt++)
                    mma_h(acc[mt][nt], alo.z, ahi.z, alo.w, ahi.w, bs[nt].z, bs[nt].w);
            }
        }
        buf++; if (buf >= 3) buf -= 3;
    }

    // ---- epilogue ----
    if (EPI == 1) {
        // stage tanh'd fp32 tile to smem, then coalesced split-fp16 writes
        __syncthreads();
        float* fs = (float*)sm;     // 128x128 fp32 = 64KB
#pragma unroll
        for (int mt = 0; mt < 4; mt++) {
#pragma unroll
            for (int nt = 0; nt < 4; nt++) {
                int r = warp_m * 64 + mt * 16 + rw;
                int c = warp_n * 32 + nt * 8 + q * 2;
                float b0 = bias[colBase + c], b1 = bias[colBase + c + 1];
                fs[r * 128 + c]           = tanhf(acc[mt][nt][0] + b0);
                fs[r * 128 + c + 1]       = tanhf(acc[mt][nt][1] + b1);
                fs[(r + 8) * 128 + c]     = tanhf(acc[mt][nt][2] + b0);
                fs[(r + 8) * 128 + c + 1] = tanhf(acc[mt][nt][3] + b1);
            }
        }
        __syncthreads();
        const int pairBase = colBase >> 1;   // multiple of 64
        const int Mw = M >> 1;               // words per hidden row
#pragma unroll
        for (int i = 0; i < 32; i++) {
            int p = tid + i * 256;           // 0..8191
            int r = p >> 6;                  // 0..127
            int kp = p & 63;                 // pair within tile
            float2 v = *(const float2*)&fs[r * 128 + kp * 2];
            uint32_t bbv, ssv;
            split2h(v.x, v.y, bbv, ssv);
            size_t dst = (size_t)(rowBase + r) * Mw + pairBase + gidx(kp);
            Hb[dst] = bbv;
            Hs[dst] = ssv;
        }
    } else {
#pragma unroll
        for (int mt = 0; mt < 4; mt++) {
#pragma unroll
            for (int nt = 0; nt < 4; nt++) {
                int row = rowBase + warp_m * 64 + mt * 16 + rw;
                int col = colBase + warp_n * 32 + nt * 8 + q * 2;
                float b0 = bias[col], b1 = bias[col + 1];
                float v0 = acc[mt][nt][0] + b0, v1 = acc[mt][nt][1] + b1;
                float v2 = acc[mt][nt][2] + b0, v3 = acc[mt][nt][3] + b1;
                *(float2*)&C[(size_t)row * M + col]       = make_float2(v0, v1);
                *(float2*)&C[(size_t)(row + 8) * M + col] = make_float2(v2, v3);
            }
        }
    }
#undef STAGE
}

// ======================= spline =======================
__global__ void __launch_bounds__(128) spline_kernel(
    const float* __restrict__ xin, int xoff,
    const float* __restrict__ params,
    float* __restrict__ z, int zoff,
    float* __restrict__ logdet, int add,
    uint32_t* __restrict__ zb, uint32_t* __restrict__ zs)
{
    const int n = blockIdx.x;
    const int d = threadIdx.x;

    __shared__ float ps[1792];
    {
        const float4* src = (const float4*)(params + (size_t)n * 1792);
#pragma unroll
        for (int i = 0; i < 3; i++)
            *(float4*)&ps[(d + i * 128) * 4] = src[d + i * 128];
        if (d < 64) *(float4*)&ps[(d + 384) * 4] = src[d + 384];
    }
    __syncthreads();

    float raw[14];
#pragma unroll
    for (int j = 0; j < 14; j++) raw[j] = ps[d * 14 + j];

    const float t = xin[(size_t)n * 256 + xoff + d];

    float cw[6], wd[5];
    {
        float m = raw[0];
#pragma unroll
        for (int j = 1; j < 5; j++) m = fmaxf(m, raw[j]);
        float e[5], s = 0.f;
#pragma unroll
        for (int j = 0; j < 5; j++) { e[j] = fexpf(raw[j] - m); s += e[j]; }
        float inv = 1.0f / s;
        float Wu[5];
#pragma unroll
        for (int j = 0; j < 5; j++) Wu[j] = 2.0f * BVAL * e[j] * inv;
        float m2 = Wu[0];
#pragma unroll
        for (int j = 1; j < 5; j++) m2 = fmaxf(m2, Wu[j]);
        float e2[5], s2 = 0.f;
#pragma unroll
        for (int j = 0; j < 5; j++) { e2[j] = fexpf(Wu[j] - m2); s2 += e2[j]; }
        float inv2 = 1.0f / s2;
        cw[0] = -BVAL;
        float run = 0.f;
#pragma unroll
        for (int j = 0; j < 5; j++) {
            float w = MIN_BW + (1.0f - MIN_BW * KBINS) * (e2[j] * inv2);
            run += w;
            cw[j + 1] = 2.0f * BVAL * run - BVAL;
        }
        cw[5] = BVAL;
#pragma unroll
        for (int j = 0; j < 5; j++) wd[j] = cw[j + 1] - cw[j];
    }

    float ch[6], hd[5];
    {
        float m = raw[5];
#pragma unroll
        for (int j = 1; j < 5; j++) m = fmaxf(m, raw[5 + j]);
        float e[5], s = 0.f;
#pragma unroll
        for (int j = 0; j < 5; j++) { e[j] = fexpf(raw[5 + j] - m); s += e[j]; }
        float inv = 1.0f / s;
        float Hu[5];
#pragma unroll
        for (int j = 0; j < 5; j++) Hu[j] = 2.0f * BVAL * e[j] * inv;
        float m2 = Hu[0];
#pragma unroll
        for (int j = 1; j < 5; j++) m2 = fmaxf(m2, Hu[j]);
        float e2[5], s2 = 0.f;
#pragma unroll
        for (int j = 0; j < 5; j++) { e2[j] = fexpf(Hu[j] - m2); s2 += e2[j]; }
        float inv2 = 1.0f / s2;
        ch[0] = -BVAL;
        float run = 0.f;
#pragma unroll
        for (int j = 0; j < 5; j++) {
            float h = MIN_BH + (1.0f - MIN_BH * KBINS) * (e2[j] * inv2);
            run += h;
            ch[j + 1] = 2.0f * BVAL * run - BVAL;
        }
        ch[5] = BVAL;
#pragma unroll
        for (int j = 0; j < 5; j++) hd[j] = ch[j + 1] - ch[j];
    }

    float deriv[6];
    deriv[0] = 1.0f;
    deriv[5] = 1.0f;
#pragma unroll
    for (int j = 0; j < 4; j++) {
        float du = fsoftplus(raw[10 + j]);
        deriv[j + 1] = MIN_DV + fsoftplus(du);
    }

    const float xc = fminf(fmaxf(t, -BVAL), BVAL);
    int cnt = 0;
#pragma unroll
    for (int j = 0; j < 6; j++) cnt += (xc >= cw[j]) ? 1 : 0;
    int idx = min(max(cnt - 1, 0), 4);

    const float icw = cw[idx], iw = wd[idx];
    const float ich = ch[idx], ih = hd[idx];
    const float delta = ih / iw;
    const float dk = deriv[idx], dk1 = deriv[idx + 1];
    const float theta = (xc - icw) / iw;
    const float t1m = theta * (1.0f - theta);
    const float num = ih * (delta * theta * theta + dk * t1m);
    const float den = delta + (dk + dk1 - 2.0f * delta) * t1m;
    const float y = ich + num / den;
    const float omt = 1.0f - theta;
    const float dnum = delta * delta * (dk1 * theta * theta + 2.0f * delta * t1m + dk * omt * omt);
    const float ld = flogf(dnum) - 2.0f * flogf(den);

    const bool inside = (t >= -BVAL) && (t <= BVAL);
    const float outv = inside ? y : t;
    const float ldv  = inside ? ld : 0.0f;

    z[(size_t)n * 256 + zoff + d] = outv;

    if (zb != nullptr) {
        float nb = __shfl_down_sync(0xffffffffu, outv, 1);
        if ((d & 1) == 0) {
            uint32_t bbv, ssv;
            split2h(outv, nb, bbv, ssv);
            int dst = n * 64 + gidx(d >> 1);
            zb[dst] = bbv;
            zs[dst] = ssv;
        }
    }

    __shared__ float red[128];
    red[d] = ldv;
    __syncthreads();
#pragma unroll
    for (int s = 64; s > 0; s >>= 1) {
        if (d < s) red[d] += red[d + s];
        __syncthreads();
    }
    if (d == 0) {
        if (add) logdet[n] += red[0];
        else     logdet[n]  = red[0];
    }
}

// ======================= host side =======================
extern "C" void kernel_launch(void* const* d_in, const int* in_sizes, int n_in,
                              void* d_out, int out_size)
{
    const float* x     = (const float*)d_in[0];
    const float* f0_w0 = (const float*)d_in[1];
    const float* f0_b0 = (const float*)d_in[2];
    const float* f0_w1 = (const float*)d_in[3];
    const float* f0_b1 = (const float*)d_in[4];
    const float* f1_w0 = (const float*)d_in[5];
    const float* f1_b0 = (const float*)d_in[6];
    const float* f1_w1 = (const float*)d_in[7];
    const float* f1_b1 = (const float*)d_in[8];

    const int N = in_sizes[0] / 256;              // 32768
    float* z      = (float*)d_out;
    float* logdet = z + (size_t)N * 256;

    uint32_t *xsb, *xss, *hb, *hs, *w0b, *w0s, *w1b, *w1s;
    float* params;
    cudaGetSymbolAddress((void**)&xsb, g_xs_big);
    cudaGetSymbolAddress((void**)&xss, g_xs_sml);
    cudaGetSymbolAddress((void**)&hb,  g_h_big);
    cudaGetSymbolAddress((void**)&hs,  g_h_sml);
    cudaGetSymbolAddress((void**)&params, g_params);
    cudaGetSymbolAddress((void**)&w0b, g_w0b);
    cudaGetSymbolAddress((void**)&w0s, g_w0s);
    cudaGetSymbolAddress((void**)&w1b, g_w1b);
    cudaGetSymbolAddress((void**)&w1s, g_w1s);

    cudaFuncSetAttribute((const void*)gemm_h3<0,0>, cudaFuncAttributeMaxDynamicSharedMemorySize, GEMM_SMEM);
    cudaFuncSetAttribute((const void*)gemm_h3<1,1>, cudaFuncAttributeMaxDynamicSharedMemorySize, GEMM_SMEM);

    const dim3 g1(512 / 128, N / 128);    // (4, 256)
    const dim3 g2(1792 / 128, N / 128);   // (14, 256)
    const int nConvBlocks = N * 64 / 256; // 8192

    // ---- coupling 1 ----
    conv_all<<<960 + nConvBlocks, 256>>>(x, 0, f0_w0, f0_w1, f1_w0, f1_w1,
                                         w0b, w0s, w1b, w1s, xsb, xss);          // 1
    gemm_h3<1,1><<<g1, 256, GEMM_SMEM>>>(xsb, xss, w0b, w0s, f0_b0,
                                         nullptr, hb, hs, 512, 64);              // 2
    gemm_h3<0,0><<<g2, 256, GEMM_SMEM>>>(hb, hs, w1b, w1s, f0_b1,
                                         params, nullptr, nullptr, 1792, 256);   // 3 (big)
    spline_kernel<<<N, 128>>>(x, 128, params, z, 128, logdet, 0, xsb, xss);      // 4 (emits split z1)

    // ---- coupling 2 ----
    gemm_h3<1,1><<<g1, 256, GEMM_SMEM>>>(xsb, xss, w0b + 512 * 64, w0s + 512 * 64,
                                         f1_b0, nullptr, hb, hs, 512, 64);       // 5
    gemm_h3<0,0><<<g2, 256, GEMM_SMEM>>>(hb, hs, w1b + 1792 * 256, w1s + 1792 * 256,
                                         f1_b1, params, nullptr, nullptr, 1792, 256); // 6 (big)
    spline_kernel<<<N, 128>>>(x, 0, params, z, 0, logdet, 1, nullptr, nullptr);  // 7
}

// round 15
// speedup vs baseline: 1.7235x; 1.0039x over previous
#include <cuda_runtime.h>
#include <cuda_fp16.h>
#include <math.h>
#include <stdint.h>

// ---------------- scratch (allocation-free: __device__ globals) ----------------
__device__ __align__(1024) uint32_t g_xs_big[32768ULL * 64];
__device__ __align__(1024) uint32_t g_xs_sml[32768ULL * 64];
__device__ __align__(1024) uint32_t g_h_big[32768ULL * 256];
__device__ __align__(1024) uint32_t g_h_sml[32768ULL * 256];
__device__ __align__(1024) float    g_params[32768ULL * 1792];
__device__ __align__(1024) uint32_t g_w0b[2][512 * 64];
__device__ __align__(1024) uint32_t g_w0s[2][512 * 64];
__device__ __align__(1024) uint32_t g_w1b[2][1792 * 256];
__device__ __align__(1024) uint32_t g_w1s[2][1792 * 256];

#define BVAL   3.0f
#define KBINS  5
#define MIN_BW 0.001f
#define MIN_BH 0.001f
#define MIN_DV 0.001f

// ======================= helpers =======================
__device__ __forceinline__ int gidx(int kpg) {
    return (kpg & ~15) | ((kpg & 3) << 2) | ((kpg >> 2) & 3);
}

__device__ __forceinline__ void split2h(float x0, float x1, uint32_t& b, uint32_t& s) {
    __half b0 = __float2half_rn(x0);
    __half b1 = __float2half_rn(x1);
    float r0 = x0 - __half2float(b0);
    float r1 = x1 - __half2float(b1);
    __half s0 = __float2half_rn(r0);
    __half s1 = __float2half_rn(r1);
    b = (uint32_t)__half_as_ushort(b0) | ((uint32_t)__half_as_ushort(b1) << 16);
    s = (uint32_t)__half_as_ushort(s0) | ((uint32_t)__half_as_ushort(s1) << 16);
}

__device__ __forceinline__ void mma_h(float* d,
                                      uint32_t a0, uint32_t a1, uint32_t a2, uint32_t a3,
                                      uint32_t b0, uint32_t b1) {
    asm volatile(
        "mma.sync.aligned.m16n8k16.row.col.f32.f16.f16.f32 "
        "{%0,%1,%2,%3}, {%4,%5,%6,%7}, {%8,%9}, {%0,%1,%2,%3};"
        : "+f"(d[0]), "+f"(d[1]), "+f"(d[2]), "+f"(d[3])
        : "r"(a0), "r"(a1), "r"(a2), "r"(a3), "r"(b0), "r"(b1));
}

#define CP16(dst, src) \
    asm volatile("cp.async.cg.shared.global [%0], [%1], 16;" :: "r"(dst), "l"(src) : "memory")
#define CP_COMMIT() asm volatile("cp.async.commit_group;" ::: "memory")
#define CP_WAIT1()  asm volatile("cp.async.wait_group 1;" ::: "memory")
#define CP_WAIT0()  asm volatile("cp.async.wait_group 0;" ::: "memory")

__device__ __forceinline__ uint32_t smem_u32(const void* p) {
    uint32_t a;
    asm("{ .reg .u64 t; cvta.to.shared.u64 t, %1; cvt.u32.u64 %0, t; }" : "=r"(a) : "l"(p));
    return a;
}

__device__ __forceinline__ float fexpf(float x) { return __expf(x); }
__device__ __forceinline__ float flogf(float x) { return __logf(x); }
__device__ __forceinline__ float fsoftplus(float x) {
    return (x > 20.0f) ? x : __logf(1.0f + __expf(x));
}

// ======================= converters =======================
__device__ __forceinline__ void conv_w_body(
    const float* __restrict__ w, int M, int K2, int m0, int kp0,
    uint32_t* __restrict__ ob, uint32_t* __restrict__ os,
    uint32_t (*tb)[33], uint32_t (*ts)[33], int tid)
{
    const int xx = tid & 31, yy = tid >> 5;
    for (int i = yy; i < 32; i += 8) {
        int kpg = kp0 + i, m = m0 + xx;
        float v0 = w[(size_t)(2 * kpg) * M + m];
        float v1 = w[(size_t)(2 * kpg + 1) * M + m];
        split2h(v0, v1, tb[i][xx], ts[i][xx]);
    }
    __syncthreads();
    for (int i = yy; i < 32; i += 8) {
        int m = m0 + i;
        size_t dst = (size_t)m * K2 + gidx(kp0 + xx);
        ob[dst] = tb[xx][i]; os[dst] = ts[xx][i];
    }
}

// One launch: all 4 weight matrices (both couplings) + x conversion.
__global__ void __launch_bounds__(256) conv_all(
    const float* __restrict__ x, int xoff,
    const float* __restrict__ w0a, const float* __restrict__ w1a,
    const float* __restrict__ w0c, const float* __restrict__ w1c,
    uint32_t* __restrict__ w0bD, uint32_t* __restrict__ w0sD,
    uint32_t* __restrict__ w1bD, uint32_t* __restrict__ w1sD,
    uint32_t* __restrict__ xb, uint32_t* __restrict__ xs)
{
    __shared__ uint32_t tb[32][33], ts[32][33];
    const int bid = blockIdx.x;
    const int tid = threadIdx.x;
    if (bid < 32) {
        conv_w_body(w0a, 512, 64, (bid & 15) * 32, (bid >> 4) * 32, w0bD, w0sD, tb, ts, tid);
    } else if (bid < 480) {
        int b = bid - 32;
        conv_w_body(w1a, 1792, 256, (b % 56) * 32, (b / 56) * 32, w1bD, w1sD, tb, ts, tid);
    } else if (bid < 512) {
        int b = bid - 480;
        conv_w_body(w0c, 512, 64, (b & 15) * 32, (b >> 4) * 32,
                    w0bD + 512 * 64, w0sD + 512 * 64, tb, ts, tid);
    } else if (bid < 960) {
        int b = bid - 512;
        conv_w_body(w1c, 1792, 256, (b % 56) * 32, (b / 56) * 32,
                    w1bD + 1792 * 256, w1sD + 1792 * 256, tb, ts, tid);
    } else {
        int t = (bid - 960) * 256 + tid;
        int row = t >> 6, kpg = t & 63;
        float2 v = *(const float2*)(x + (size_t)row * 256 + xoff + 2 * kpg);
        uint32_t b_, s_;
        split2h(v.x, v.y, b_, s_);
        int dst = row * 64 + gidx(kpg);
        xb[dst] = b_; xs[dst] = s_;
    }
}

// ======================= fp16 split tensor-core GEMM =======================
// Block 128x128 (BK=16 words=32k), 256 threads (8 warps 2x4), warp 64x32.
// TERM3=1: 3-term (GEMM1, accuracy). TERM3=0: 2-term (GEMM2, at HMMA floor).
// EPI=1: tanh + split-fp16 via smem-staged coalesced writes to Hb/Hs.
#define GEMM_SMEM (3 * 32768)

template <int EPI, int TERM3>
__global__ void __launch_bounds__(256, 2) gemm_h3(
    const uint32_t* __restrict__ Ab, const uint32_t* __restrict__ As,
    const uint32_t* __restrict__ Bb, const uint32_t* __restrict__ Bs,
    const float* __restrict__ bias,
    float* __restrict__ C, uint32_t* __restrict__ Hb, uint32_t* __restrict__ Hs,
    int M, int K2)
{
    extern __shared__ uint32_t sm[];
    const uint32_t sbase = smem_u32(sm);
    const int tid  = threadIdx.x;
    const int lane = tid & 31;
    const int wid  = tid >> 5;
    const int warp_m = wid & 1;
    const int warp_n = wid >> 1;
    const int rowBase = blockIdx.y * 128;
    const int colBase = blockIdx.x * 128;
    const int q  = lane & 3;
    const int rw = lane >> 2;

    const int cr  = tid >> 1;
    const int cw8 = (tid & 1) * 8;
    const uint32_t* gAb = Ab + (size_t)(rowBase + cr) * K2 + cw8;
    const uint32_t* gAs = As + (size_t)(rowBase + cr) * K2 + cw8;
    const uint32_t* gBb = Bb + (size_t)(colBase + cr) * K2 + cw8;
    const uint32_t* gBs = Bs + (size_t)(colBase + cr) * K2 + cw8;
    const uint32_t sdst = sbase + (uint32_t)(cr * 16 + cw8) * 4;

#define STAGE(it, buf) do { \
        uint32_t d0 = sdst + (uint32_t)(buf) * 32768u; \
        const uint32_t* pa = gAb + (it) * 16; \
        const uint32_t* ps = gAs + (it) * 16; \
        const uint32_t* pb = gBb + (it) * 16; \
        CP16(d0,          pa); CP16(d0 + 16,          pa + 4); \
        CP16(d0 + 8192,   ps); CP16(d0 + 8192 + 16,   ps + 4); \
        CP16(d0 + 16384,  pb); CP16(d0 + 16384 + 16,  pb + 4); \
        if (TERM3) { \
            const uint32_t* pq = gBs + (it) * 16; \
            CP16(d0 + 24576,  pq); CP16(d0 + 24576 + 16,  pq + 4); \
        } \
        CP_COMMIT(); \
    } while (0)

    float acc[4][4][4];
#pragma unroll
    for (int mt = 0; mt < 4; mt++)
#pragma unroll
        for (int nt = 0; nt < 4; nt++)
#pragma unroll
            for (int c = 0; c < 4; c++) acc[mt][nt][c] = 0.f;

    const int nIter = K2 >> 4;
    STAGE(0, 0);
    STAGE(1, 1);

    int buf = 0;
    for (int it = 0; it < nIter; it++) {
        if (it + 1 < nIter) { CP_WAIT1(); } else { CP_WAIT0(); }
        __syncthreads();
        if (it + 2 < nIter) {
            int nb = buf + 2; if (nb >= 3) nb -= 3;
            STAGE(it + 2, nb);
        }
        const uint32_t* sA = sm + buf * 8192;
        const uint32_t* sB = sA + 4096;

        uint4 bb[4], bs[4];
#pragma unroll
        for (int nt = 0; nt < 4; nt++) {
            const uint32_t* p = sB + (warp_n * 32 + nt * 8 + rw) * 16 + 4 * q;
            bb[nt] = *(const uint4*)p;
            if (TERM3) bs[nt] = *(const uint4*)(p + 2048);
        }
#pragma unroll
        for (int mt = 0; mt < 4; mt++) {
            const uint32_t* p = sA + (warp_m * 64 + mt * 16 + rw) * 16 + 4 * q;
            uint4 alo = *(const uint4*)p;
            uint4 ahi = *(const uint4*)(p + 128);
            uint4 slo = *(const uint4*)(p + 2048);
            uint4 shi = *(const uint4*)(p + 2048 + 128);
#pragma unroll
            for (int nt = 0; nt < 4; nt++)
                mma_h(acc[mt][nt], alo.x, ahi.x, alo.y, ahi.y, bb[nt].x, bb[nt].y);
#pragma unroll
            for (int nt = 0; nt < 4; nt++)
                mma_h(acc[mt][nt], alo.z, ahi.z, alo.w, ahi.w, bb[nt].z, bb[nt].w);
#pragma unroll
            for (int nt = 0; nt < 4; nt++)
                mma_h(acc[mt][nt], slo.x, shi.x, slo.y, shi.y, bb[nt].x, bb[nt].y);
#pragma unroll
            for (int nt = 0; nt < 4; nt++)
                mma_h(acc[mt][nt], slo.z, shi.z, slo.w, shi.w, bb[nt].z, bb[nt].w);
            if (TERM3) {
#pragma unroll
                for (int nt = 0; nt < 4; nt++)
                    mma_h(acc[mt][nt], alo.x, ahi.x, alo.y, ahi.y, bs[nt].x, bs[nt].y);
#pragma unroll
                for (int nt = 0; nt < 4; nt++)
                    mma_h(acc[mt][nt], alo.z, ahi.z, alo.w, ahi.w, bs[nt].z, bs[nt].w);
            }
        }
        buf++; if (buf >= 3) buf -= 3;
    }

    // ---- epilogue ----
    if (EPI == 1) {
        __syncthreads();
        float* fs = (float*)sm;     // 128x128 fp32 = 64KB
#pragma unroll
        for (int mt = 0; mt < 4; mt++) {
#pragma unroll
            for (int nt = 0; nt < 4; nt++) {
                int r = warp_m * 64 + mt * 16 + rw;
                int c = warp_n * 32 + nt * 8 + q * 2;
                float b0 = bias[colBase + c], b1 = bias[colBase + c + 1];
                fs[r * 128 + c]           = tanhf(acc[mt][nt][0] + b0);
                fs[r * 128 + c + 1]       = tanhf(acc[mt][nt][1] + b1);
                fs[(r + 8) * 128 + c]     = tanhf(acc[mt][nt][2] + b0);
                fs[(r + 8) * 128 + c + 1] = tanhf(acc[mt][nt][3] + b1);
            }
        }
        __syncthreads();
        const int pairBase = colBase >> 1;
        const int Mw = M >> 1;
#pragma unroll
        for (int i = 0; i < 32; i++) {
            int p = tid + i * 256;
            int r = p >> 6;
            int kp = p & 63;
            float2 v = *(const float2*)&fs[r * 128 + kp * 2];
            uint32_t bbv, ssv;
            split2h(v.x, v.y, bbv, ssv);
            size_t dst = (size_t)(rowBase + r) * Mw + pairBase + gidx(kp);
            Hb[dst] = bbv;
            Hs[dst] = ssv;
        }
    } else {
#pragma unroll
        for (int mt = 0; mt < 4; mt++) {
#pragma unroll
            for (int nt = 0; nt < 4; nt++) {
                int row = rowBase + warp_m * 64 + mt * 16 + rw;
                int col = colBase + warp_n * 32 + nt * 8 + q * 2;
                float b0 = bias[col], b1 = bias[col + 1];
                float v0 = acc[mt][nt][0] + b0, v1 = acc[mt][nt][1] + b1;
                float v2 = acc[mt][nt][2] + b0, v3 = acc[mt][nt][3] + b1;
                *(float2*)&C[(size_t)row * M + col]       = make_float2(v0, v1);
                *(float2*)&C[(size_t)(row + 8) * M + col] = make_float2(v2, v3);
            }
        }
    }
#undef STAGE
}

// ======================= spline (2 rows/block, warp-shuffle reduction) =======================
__global__ void __launch_bounds__(256) spline_kernel(
    const float* __restrict__ xin, int xoff,
    const float* __restrict__ params,
    float* __restrict__ z, int zoff,
    float* __restrict__ logdet, int add,
    uint32_t* __restrict__ zb, uint32_t* __restrict__ zs)
{
    const int n0  = blockIdx.x * 2;
    const int tid = threadIdx.x;
    const int half = tid >> 7;         // row within block
    const int d = tid & 127;
    const int n = n0 + half;

    __shared__ float ps[2 * 1792];
    {
        const float4* src = (const float4*)(params + (size_t)n0 * 1792);
        float4* dst = (float4*)ps;
#pragma unroll
        for (int i = 0; i < 3; i++) dst[tid + i * 256] = src[tid + i * 256];
        if (tid < 128) dst[tid + 768] = src[tid + 768];
    }
    __syncthreads();

    float raw[14];
#pragma unroll
    for (int j = 0; j < 14; j++) raw[j] = ps[half * 1792 + d * 14 + j];

    const float t = xin[(size_t)n * 256 + xoff + d];

    float cw[6], wd[5];
    {
        float m = raw[0];
#pragma unroll
        for (int j = 1; j < 5; j++) m = fmaxf(m, raw[j]);
        float e[5], s = 0.f;
#pragma unroll
        for (int j = 0; j < 5; j++) { e[j] = fexpf(raw[j] - m); s += e[j]; }
        float inv = __fdividef(1.0f, s);
        float Wu[5];
#pragma unroll
        for (int j = 0; j < 5; j++) Wu[j] = 2.0f * BVAL * e[j] * inv;
        float m2 = Wu[0];
#pragma unroll
        for (int j = 1; j < 5; j++) m2 = fmaxf(m2, Wu[j]);
        float e2[5], s2 = 0.f;
#pragma unroll
        for (int j = 0; j < 5; j++) { e2[j] = fexpf(Wu[j] - m2); s2 += e2[j]; }
        float inv2 = __fdividef(1.0f, s2);
        cw[0] = -BVAL;
        float run = 0.f;
#pragma unroll
        for (int j = 0; j < 5; j++) {
            float w = MIN_BW + (1.0f - MIN_BW * KBINS) * (e2[j] * inv2);
            run += w;
            cw[j + 1] = 2.0f * BVAL * run - BVAL;
        }
        cw[5] = BVAL;
#pragma unroll
        for (int j = 0; j < 5; j++) wd[j] = cw[j + 1] - cw[j];
    }

    float ch[6], hd[5];
    {
        float m = raw[5];
#pragma unroll
        for (int j = 1; j < 5; j++) m = fmaxf(m, raw[5 + j]);
        float e[5], s = 0.f;
#pragma unroll
        for (int j = 0; j < 5; j++) { e[j] = fexpf(raw[5 + j] - m); s += e[j]; }
        float inv = __fdividef(1.0f, s);
        float Hu[5];
#pragma unroll
        for (int j = 0; j < 5; j++) Hu[j] = 2.0f * BVAL * e[j] * inv;
        float m2 = Hu[0];
#pragma unroll
        for (int j = 1; j < 5; j++) m2 = fmaxf(m2, Hu[j]);
        float e2[5], s2 = 0.f;
#pragma unroll
        for (int j = 0; j < 5; j++) { e2[j] = fexpf(Hu[j] - m2); s2 += e2[j]; }
        float inv2 = __fdividef(1.0f, s2);
        ch[0] = -BVAL;
        float run = 0.f;
#pragma unroll
        for (int j = 0; j < 5; j++) {
            float h = MIN_BH + (1.0f - MIN_BH * KBINS) * (e2[j] * inv2);
            run += h;
            ch[j + 1] = 2.0f * BVAL * run - BVAL;
        }
        ch[5] = BVAL;
#pragma unroll
        for (int j = 0; j < 5; j++) hd[j] = ch[j + 1] - ch[j];
    }

    float deriv[6];
    deriv[0] = 1.0f;
    deriv[5] = 1.0f;
#pragma unroll
    for (int j = 0; j < 4; j++) {
        float du = fsoftplus(raw[10 + j]);
        deriv[j + 1] = MIN_DV + fsoftplus(du);
    }

    const float xc = fminf(fmaxf(t, -BVAL), BVAL);
    int cnt = 0;
#pragma unroll
    for (int j = 0; j < 6; j++) cnt += (xc >= cw[j]) ? 1 : 0;
    int idx = min(max(cnt - 1, 0), 4);

    const float icw = cw[idx], iw = wd[idx];
    const float ich = ch[idx], ih = hd[idx];
    const float delta = __fdividef(ih, iw);
    const float dk = deriv[idx], dk1 = deriv[idx + 1];
    const float theta = __fdividef(xc - icw, iw);
    const float t1m = theta * (1.0f - theta);
    const float num = ih * (delta * theta * theta + dk * t1m);
    const float den = delta + (dk + dk1 - 2.0f * delta) * t1m;
    const float y = ich + __fdividef(num, den);
    const float omt = 1.0f - theta;
    const float dnum = delta * delta * (dk1 * theta * theta + 2.0f * delta * t1m + dk * omt * omt);
    const float ld = flogf(__fdividef(dnum, den * den));

    const bool inside = (t >= -BVAL) && (t <= BVAL);
    const float outv = inside ? y : t;
    const float ldv  = inside ? ld : 0.0f;

    z[(size_t)n * 256 + zoff + d] = outv;

    if (zb != nullptr) {
        float nb = __shfl_down_sync(0xffffffffu, outv, 1);
        if ((d & 1) == 0) {
            uint32_t bbv, ssv;
            split2h(outv, nb, bbv, ssv);
            int dst = n * 64 + gidx(d >> 1);
            zb[dst] = bbv;
            zs[dst] = ssv;
        }
    }

    // warp-shuffle reduction: 8 warps -> 8 partials -> 2 rows
    float v = ldv;
#pragma unroll
    for (int o = 16; o > 0; o >>= 1) v += __shfl_xor_sync(0xffffffffu, v, o);
    __shared__ float red[8];
    if ((tid & 31) == 0) red[tid >> 5] = v;
    __syncthreads();
    if (tid == 0) {
        float s = red[0] + red[1] + red[2] + red[3];
        if (add) logdet[n0] += s; else logdet[n0] = s;
    } else if (tid == 128) {
        float s = red[4] + red[5] + red[6] + red[7];
        if (add) logdet[n0 + 1] += s; else logdet[n0 + 1] = s;
    }
}

// ======================= host side =======================
extern "C" void kernel_launch(void* const* d_in, const int* in_sizes, int n_in,
                              void* d_out, int out_size)
{
    const float* x     = (const float*)d_in[0];
    const float* f0_w0 = (const float*)d_in[1];
    const float* f0_b0 = (const float*)d_in[2];
    const float* f0_w1 = (const float*)d_in[3];
    const float* f0_b1 = (const float*)d_in[4];
    const float* f1_w0 = (const float*)d_in[5];
    const float* f1_b0 = (const float*)d_in[6];
    const float* f1_w1 = (const float*)d_in[7];
    const float* f1_b1 = (const float*)d_in[8];

    const int N = in_sizes[0] / 256;              // 32768
    float* z      = (float*)d_out;
    float* logdet = z + (size_t)N * 256;

    uint32_t *xsb, *xss, *hb, *hs, *w0b, *w0s, *w1b, *w1s;
    float* params;
    cudaGetSymbolAddress((void**)&xsb, g_xs_big);
    cudaGetSymbolAddress((void**)&xss, g_xs_sml);
    cudaGetSymbolAddress((void**)&hb,  g_h_big);
    cudaGetSymbolAddress((void**)&hs,  g_h_sml);
    cudaGetSymbolAddress((void**)&params, g_params);
    cudaGetSymbolAddress((void**)&w0b, g_w0b);
    cudaGetSymbolAddress((void**)&w0s, g_w0s);
    cudaGetSymbolAddress((void**)&w1b, g_w1b);
    cudaGetSymbolAddress((void**)&w1s, g_w1s);

    cudaFuncSetAttribute((const void*)gemm_h3<0,0>, cudaFuncAttributeMaxDynamicSharedMemorySize, GEMM_SMEM);
    cudaFuncSetAttribute((const void*)gemm_h3<1,1>, cudaFuncAttributeMaxDynamicSharedMemorySize, GEMM_SMEM);

    const dim3 g1(512 / 128, N / 128);    // (4, 256)
    const dim3 g2(1792 / 128, N / 128);   // (14, 256)
    const int nConvBlocks = N * 64 / 256; // 8192

    // ---- coupling 1 ----
    conv_all<<<960 + nConvBlocks, 256>>>(x, 0, f0_w0, f0_w1, f1_w0, f1_w1,
                                         w0b, w0s, w1b, w1s, xsb, xss);          // 1
    gemm_h3<1,1><<<g1, 256, GEMM_SMEM>>>(xsb, xss, w0b, w0s, f0_b0,
                                         nullptr, hb, hs, 512, 64);              // 2
    gemm_h3<0,0><<<g2, 256, GEMM_SMEM>>>(hb, hs, w1b, w1s, f0_b1,
                                         params, nullptr, nullptr, 1792, 256);   // 3 (big)
    spline_kernel<<<N / 2, 256>>>(x, 128, params, z, 128, logdet, 0, xsb, xss);  // 4 (emits split z1)

    // ---- coupling 2 ----
    gemm_h3<1,1><<<g1, 256, GEMM_SMEM>>>(xsb, xss, w0b + 512 * 64, w0s + 512 * 64,
                                         f1_b0, nullptr, hb, hs, 512, 64);       // 5
    gemm_h3<0,0><<<g2, 256, GEMM_SMEM>>>(hb, hs, w1b + 1792 * 256, w1s + 1792 * 256,
                                         f1_b1, params, nullptr, nullptr, 1792, 256); // 6 (big)
    spline_kernel<<<N / 2, 256>>>(x, 0, params, z, 0, logdet, 1, nullptr, nullptr);   // 7
}

// round 16
// speedup vs baseline: 1.8760x; 1.0885x over previous
#include <cuda_runtime.h>
#include <cuda_fp16.h>
#include <math.h>
#include <stdint.h>

// ---------------- scratch (allocation-free: __device__ globals) ----------------
__device__ __align__(1024) uint32_t g_xs_big[32768ULL * 64];
__device__ __align__(1024) uint32_t g_xs_sml[32768ULL * 64];
__device__ __align__(1024) uint32_t g_h_big[32768ULL * 256];
__device__ __align__(1024) uint32_t g_h_sml[32768ULL * 256];
__device__ __align__(1024) uint32_t g_w0b[2][512 * 64];
__device__ __align__(1024) uint32_t g_w0s[2][512 * 64];
__device__ __align__(1024) uint32_t g_w1b[2][1792 * 256];
__device__ __align__(1024) uint32_t g_w1s[2][1792 * 256];
__device__ __align__(1024) float    g_ldp[2][32768ULL * 16];   // per-(row, colblock) logdet partials

#define BVAL   3.0f
#define KBINS  5
#define MIN_BW 0.001f
#define MIN_BH 0.001f
#define MIN_DV 0.001f

// ======================= helpers =======================
__device__ __forceinline__ int gidx(int kpg) {
    return (kpg & ~15) | ((kpg & 3) << 2) | ((kpg >> 2) & 3);
}

__device__ __forceinline__ void split2h(float x0, float x1, uint32_t& b, uint32_t& s) {
    __half b0 = __float2half_rn(x0);
    __half b1 = __float2half_rn(x1);
    float r0 = x0 - __half2float(b0);
    float r1 = x1 - __half2float(b1);
    __half s0 = __float2half_rn(r0);
    __half s1 = __float2half_rn(r1);
    b = (uint32_t)__half_as_ushort(b0) | ((uint32_t)__half_as_ushort(b1) << 16);
    s = (uint32_t)__half_as_ushort(s0) | ((uint32_t)__half_as_ushort(s1) << 16);
}

__device__ __forceinline__ void mma_h(float* d,
                                      uint32_t a0, uint32_t a1, uint32_t a2, uint32_t a3,
                                      uint32_t b0, uint32_t b1) {
    asm volatile(
        "mma.sync.aligned.m16n8k16.row.col.f32.f16.f16.f32 "
        "{%0,%1,%2,%3}, {%4,%5,%6,%7}, {%8,%9}, {%0,%1,%2,%3};"
        : "+f"(d[0]), "+f"(d[1]), "+f"(d[2]), "+f"(d[3])
        : "r"(a0), "r"(a1), "r"(a2), "r"(a3), "r"(b0), "r"(b1));
}

#define CP16(dst, src) \
    asm volatile("cp.async.cg.shared.global [%0], [%1], 16;" :: "r"(dst), "l"(src) : "memory")
#define CP_COMMIT() asm volatile("cp.async.commit_group;" ::: "memory")
#define CP_WAIT1()  asm volatile("cp.async.wait_group 1;" ::: "memory")
#define CP_WAIT0()  asm volatile("cp.async.wait_group 0;" ::: "memory")

__device__ __forceinline__ uint32_t smem_u32(const void* p) {
    uint32_t a;
    asm("{ .reg .u64 t; cvta.to.shared.u64 t, %1; cvt.u32.u64 %0, t; }" : "=r"(a) : "l"(p));
    return a;
}

__device__ __forceinline__ float fexpf(float x) { return __expf(x); }
__device__ __forceinline__ float flogf(float x) { return __logf(x); }
__device__ __forceinline__ float fsoftplus(float x) {
    return (x > 20.0f) ? x : __logf(1.0f + __expf(x));
}

// rational-quadratic spline for one element; raw = 14 params, t = input.
// Returns y; *ldOut = log-det term. Identical arithmetic to round-15 spline.
__device__ __forceinline__ float spline_eval(const float* raw, float t, float* ldOut) {
    float cw[6], wd[5];
    {
        float m = raw[0];
#pragma unroll
        for (int j = 1; j < 5; j++) m = fmaxf(m, raw[j]);
        float e[5], s = 0.f;
#pragma unroll
        for (int j = 0; j < 5; j++) { e[j] = fexpf(raw[j] - m); s += e[j]; }
        float inv = __fdividef(1.0f, s);
        float Wu[5];
#pragma unroll
        for (int j = 0; j < 5; j++) Wu[j] = 2.0f * BVAL * e[j] * inv;
        float m2 = Wu[0];
#pragma unroll
        for (int j = 1; j < 5; j++) m2 = fmaxf(m2, Wu[j]);
        float e2[5], s2 = 0.f;
#pragma unroll
        for (int j = 0; j < 5; j++) { e2[j] = fexpf(Wu[j] - m2); s2 += e2[j]; }
        float inv2 = __fdividef(1.0f, s2);
        cw[0] = -BVAL;
        float run = 0.f;
#pragma unroll
        for (int j = 0; j < 5; j++) {
            float w = MIN_BW + (1.0f - MIN_BW * KBINS) * (e2[j] * inv2);
            run += w;
            cw[j + 1] = 2.0f * BVAL * run - BVAL;
        }
        cw[5] = BVAL;
#pragma unroll
        for (int j = 0; j < 5; j++) wd[j] = cw[j + 1] - cw[j];
    }
    float ch[6], hd[5];
    {
        float m = raw[5];
#pragma unroll
        for (int j = 1; j < 5; j++) m = fmaxf(m, raw[5 + j]);
        float e[5], s = 0.f;
#pragma unroll
        for (int j = 0; j < 5; j++) { e[j] = fexpf(raw[5 + j] - m); s += e[j]; }
        float inv = __fdividef(1.0f, s);
        float Hu[5];
#pragma unroll
        for (int j = 0; j < 5; j++) Hu[j] = 2.0f * BVAL * e[j] * inv;
        float m2 = Hu[0];
#pragma unroll
        for (int j = 1; j < 5; j++) m2 = fmaxf(m2, Hu[j]);
        float e2[5], s2 = 0.f;
#pragma unroll
        for (int j = 0; j < 5; j++) { e2[j] = fexpf(Hu[j] - m2); s2 += e2[j]; }
        float inv2 = __fdividef(1.0f, s2);
        ch[0] = -BVAL;
        float run = 0.f;
#pragma unroll
        for (int j = 0; j < 5; j++) {
            float h = MIN_BH + (1.0f - MIN_BH * KBINS) * (e2[j] * inv2);
            run += h;
            ch[j + 1] = 2.0f * BVAL * run - BVAL;
        }
        ch[5] = BVAL;
#pragma unroll
        for (int j = 0; j < 5; j++) hd[j] = ch[j + 1] - ch[j];
    }
    float deriv[6];
    deriv[0] = 1.0f;
    deriv[5] = 1.0f;
#pragma unroll
    for (int j = 0; j < 4; j++) {
        float du = fsoftplus(raw[10 + j]);
        deriv[j + 1] = MIN_DV + fsoftplus(du);
    }
    const float xc = fminf(fmaxf(t, -BVAL), BVAL);
    int cnt = 0;
#pragma unroll
    for (int j = 0; j < 6; j++) cnt += (xc >= cw[j]) ? 1 : 0;
    int idx = min(max(cnt - 1, 0), 4);

    const float icw = cw[idx], iw = wd[idx];
    const float ich = ch[idx], ih = hd[idx];
    const float delta = __fdividef(ih, iw);
    const float dk = deriv[idx], dk1 = deriv[idx + 1];
    const float theta = __fdividef(xc - icw, iw);
    const float t1m = theta * (1.0f - theta);
    const float num = ih * (delta * theta * theta + dk * t1m);
    const float den = delta + (dk + dk1 - 2.0f * delta) * t1m;
    const float y = ich + __fdividef(num, den);
    const float omt = 1.0f - theta;
    const float dnum = delta * delta * (dk1 * theta * theta + 2.0f * delta * t1m + dk * omt * omt);
    const float ld = flogf(__fdividef(dnum, den * den));

    const bool inside = (t >= -BVAL) && (t <= BVAL);
    *ldOut = inside ? ld : 0.0f;
    return inside ? y : t;
}

// ======================= converters =======================
__device__ __forceinline__ void conv_w_body(
    const float* __restrict__ w, int M, int K2, int m0, int kp0,
    uint32_t* __restrict__ ob, uint32_t* __restrict__ os,
    uint32_t (*tb)[33], uint32_t (*ts)[33], int tid)
{
    const int xx = tid & 31, yy = tid >> 5;
    for (int i = yy; i < 32; i += 8) {
        int kpg = kp0 + i, m = m0 + xx;
        float v0 = w[(size_t)(2 * kpg) * M + m];
        float v1 = w[(size_t)(2 * kpg + 1) * M + m];
        split2h(v0, v1, tb[i][xx], ts[i][xx]);
    }
    __syncthreads();
    for (int i = yy; i < 32; i += 8) {
        int m = m0 + i;
        size_t dst = (size_t)m * K2 + gidx(kp0 + xx);
        ob[dst] = tb[xx][i]; os[dst] = ts[xx][i];
    }
}

__global__ void __launch_bounds__(256) conv_all(
    const float* __restrict__ x, int xoff,
    const float* __restrict__ w0a, const float* __restrict__ w1a,
    const float* __restrict__ w0c, const float* __restrict__ w1c,
    uint32_t* __restrict__ w0bD, uint32_t* __restrict__ w0sD,
    uint32_t* __restrict__ w1bD, uint32_t* __restrict__ w1sD,
    uint32_t* __restrict__ xb, uint32_t* __restrict__ xs)
{
    __shared__ uint32_t tb[32][33], ts[32][33];
    const int bid = blockIdx.x;
    const int tid = threadIdx.x;
    if (bid < 32) {
        conv_w_body(w0a, 512, 64, (bid & 15) * 32, (bid >> 4) * 32, w0bD, w0sD, tb, ts, tid);
    } else if (bid < 480) {
        int b = bid - 32;
        conv_w_body(w1a, 1792, 256, (b % 56) * 32, (b / 56) * 32, w1bD, w1sD, tb, ts, tid);
    } else if (bid < 512) {
        int b = bid - 480;
        conv_w_body(w0c, 512, 64, (b & 15) * 32, (b >> 4) * 32,
                    w0bD + 512 * 64, w0sD + 512 * 64, tb, ts, tid);
    } else if (bid < 960) {
        int b = bid - 512;
        conv_w_body(w1c, 1792, 256, (b % 56) * 32, (b / 56) * 32,
                    w1bD + 1792 * 256, w1sD + 1792 * 256, tb, ts, tid);
    } else {
        int t = (bid - 960) * 256 + tid;
        int row = t >> 6, kpg = t & 63;
        float2 v = *(const float2*)(x + (size_t)row * 256 + xoff + 2 * kpg);
        uint32_t b_, s_;
        split2h(v.x, v.y, b_, s_);
        int dst = row * 64 + gidx(kpg);
        xb[dst] = b_; xs[dst] = s_;
    }
}

// ======================= GEMM1: fp16 3-term, EPI -> tanh + split-fp16 =======================
#define GEMM_SMEM (3 * 32768)

__global__ void __launch_bounds__(256, 2) gemm1_h3(
    const uint32_t* __restrict__ Ab, const uint32_t* __restrict__ As,
    const uint32_t* __restrict__ Bb, const uint32_t* __restrict__ Bs,
    const float* __restrict__ bias,
    uint32_t* __restrict__ Hb, uint32_t* __restrict__ Hs,
    int M, int K2)
{
    extern __shared__ uint32_t sm[];
    const uint32_t sbase = smem_u32(sm);
    const int tid  = threadIdx.x;
    const int lane = tid & 31;
    const int wid  = tid >> 5;
    const int warp_m = wid & 1;
    const int warp_n = wid >> 1;
    const int rowBase = blockIdx.y * 128;
    const int colBase = blockIdx.x * 128;
    const int q  = lane & 3;
    const int rw = lane >> 2;

    const int cr  = tid >> 1;
    const int cw8 = (tid & 1) * 8;
    const uint32_t* gAb = Ab + (size_t)(rowBase + cr) * K2 + cw8;
    const uint32_t* gAs = As + (size_t)(rowBase + cr) * K2 + cw8;
    const uint32_t* gBb = Bb + (size_t)(colBase + cr) * K2 + cw8;
    const uint32_t* gBs = Bs + (size_t)(colBase + cr) * K2 + cw8;
    const uint32_t sdst = sbase + (uint32_t)(cr * 16 + cw8) * 4;

#define STAGE1(it, buf) do { \
        uint32_t d0 = sdst + (uint32_t)(buf) * 32768u; \
        CP16(d0,          gAb + (it) * 16); CP16(d0 + 16,          gAb + (it) * 16 + 4); \
        CP16(d0 + 8192,   gAs + (it) * 16); CP16(d0 + 8192 + 16,   gAs + (it) * 16 + 4); \
        CP16(d0 + 16384,  gBb + (it) * 16); CP16(d0 + 16384 + 16,  gBb + (it) * 16 + 4); \
        CP16(d0 + 24576,  gBs + (it) * 16); CP16(d0 + 24576 + 16,  gBs + (it) * 16 + 4); \
        CP_COMMIT(); \
    } while (0)

    float acc[4][4][4];
#pragma unroll
    for (int mt = 0; mt < 4; mt++)
#pragma unroll
        for (int nt = 0; nt < 4; nt++)
#pragma unroll
            for (int c = 0; c < 4; c++) acc[mt][nt][c] = 0.f;

    const int nIter = K2 >> 4;   // 4
    STAGE1(0, 0);
    STAGE1(1, 1);

    int buf = 0;
    for (int it = 0; it < nIter; it++) {
        if (it + 1 < nIter) { CP_WAIT1(); } else { CP_WAIT0(); }
        __syncthreads();
        if (it + 2 < nIter) {
            int nb = buf + 2; if (nb >= 3) nb -= 3;
            STAGE1(it + 2, nb);
        }
        const uint32_t* sA = sm + buf * 8192;
        const uint32_t* sB = sA + 4096;

        uint4 bb[4], bs[4];
#pragma unroll
        for (int nt = 0; nt < 4; nt++) {
            const uint32_t* p = sB + (warp_n * 32 + nt * 8 + rw) * 16 + 4 * q;
            bb[nt] = *(const uint4*)p;
            bs[nt] = *(const uint4*)(p + 2048);
        }
#pragma unroll
        for (int mt = 0; mt < 4; mt++) {
            const uint32_t* p = sA + (warp_m * 64 + mt * 16 + rw) * 16 + 4 * q;
            uint4 alo = *(const uint4*)p;
            uint4 ahi = *(const uint4*)(p + 128);
            uint4 slo = *(const uint4*)(p + 2048);
            uint4 shi = *(const uint4*)(p + 2048 + 128);
#pragma unroll
            for (int nt = 0; nt < 4; nt++)
                mma_h(acc[mt][nt], alo.x, ahi.x, alo.y, ahi.y, bb[nt].x, bb[nt].y);
#pragma unroll
            for (int nt = 0; nt < 4; nt++)
                mma_h(acc[mt][nt], alo.z, ahi.z, alo.w, ahi.w, bb[nt].z, bb[nt].w);
#pragma unroll
            for (int nt = 0; nt < 4; nt++)
                mma_h(acc[mt][nt], slo.x, shi.x, slo.y, shi.y, bb[nt].x, bb[nt].y);
#pragma unroll
            for (int nt = 0; nt < 4; nt++)
                mma_h(acc[mt][nt], slo.z, shi.z, slo.w, shi.w, bb[nt].z, bb[nt].w);
#pragma unroll
            for (int nt = 0; nt < 4; nt++)
                mma_h(acc[mt][nt], alo.x, ahi.x, alo.y, ahi.y, bs[nt].x, bs[nt].y);
#pragma unroll
            for (int nt = 0; nt < 4; nt++)
                mma_h(acc[mt][nt], alo.z, ahi.z, alo.w, ahi.w, bs[nt].z, bs[nt].w);
        }
        buf++; if (buf >= 3) buf -= 3;
    }

    // tanh + split-fp16, smem-staged coalesced writes
    __syncthreads();
    float* fs = (float*)sm;
#pragma unroll
    for (int mt = 0; mt < 4; mt++) {
#pragma unroll
        for (int nt = 0; nt < 4; nt++) {
            int r = warp_m * 64 + mt * 16 + rw;
            int c = warp_n * 32 + nt * 8 + q * 2;
            float b0 = bias[colBase + c], b1 = bias[colBase + c + 1];
            fs[r * 128 + c]           = tanhf(acc[mt][nt][0] + b0);
            fs[r * 128 + c + 1]       = tanhf(acc[mt][nt][1] + b1);
            fs[(r + 8) * 128 + c]     = tanhf(acc[mt][nt][2] + b0);
            fs[(r + 8) * 128 + c + 1] = tanhf(acc[mt][nt][3] + b1);
        }
    }
    __syncthreads();
    const int pairBase = colBase >> 1;
    const int Mw = M >> 1;
#pragma unroll
    for (int i = 0; i < 32; i++) {
        int p = tid + i * 256;
        int r = p >> 6;
        int kp = p & 63;
        float2 v = *(const float2*)&fs[r * 128 + kp * 2];
        uint32_t bbv, ssv;
        split2h(v.x, v.y, bbv, ssv);
        size_t dst = (size_t)(rowBase + r) * Mw + pairBase + gidx(kp);
        Hb[dst] = bbv;
        Hs[dst] = ssv;
    }
#undef STAGE1
}

// ======================= GEMM2 fused with spline =======================
// Block tile 128 rows x 112 cols (= 8 complete 14-param spline groups).
// 256 threads, 8 warps (4m x 2n), warp tile 32x56. 2-term (Ab*Bb + As*Bb).
// Epilogue: bias -> smem fs[128][113] -> in-block spline for 1024 (row,d2)
// pairs -> z write, optional split-z emit, per-(row,colblock) logdet partials.
#define G2_SMEM (3 * 24576)

__global__ void __launch_bounds__(256, 2) gemm2_fused(
    const uint32_t* __restrict__ Ab, const uint32_t* __restrict__ As,
    const uint32_t* __restrict__ Bb,
    const float* __restrict__ bias,
    const float* __restrict__ x, int xoff,
    float* __restrict__ z, int zoff,
    uint32_t* __restrict__ zb, uint32_t* __restrict__ zs,
    float* __restrict__ ldpart)
{
    extern __shared__ uint32_t sm[];
    const uint32_t sbase = smem_u32(sm);
    const int tid  = threadIdx.x;
    const int lane = tid & 31;
    const int wid  = tid >> 5;
    const int warp_m = wid & 3;        // 0..3 (32 rows each)
    const int warp_n = wid >> 2;       // 0..1 (56 cols each)
    const int bx = blockIdx.x;         // col block 0..15
    const int rowBase = blockIdx.y * 128;
    const int colBase = bx * 112;
    const int q  = lane & 3;
    const int rw = lane >> 2;
    const int K2 = 256;

    const int cr  = tid >> 1;
    const int cw8 = (tid & 1) * 8;
    const uint32_t* gAb = Ab + (size_t)(rowBase + cr) * K2 + cw8;
    const uint32_t* gAs = As + (size_t)(rowBase + cr) * K2 + cw8;
    const uint32_t* gBb = Bb + (size_t)(colBase + cr) * K2 + cw8;
    const uint32_t sdst = sbase + (uint32_t)(cr * 16 + cw8) * 4;
    const bool doB = (cr < 112);

#define STAGE2(it, buf) do { \
        uint32_t d0 = sdst + (uint32_t)(buf) * 24576u; \
        CP16(d0,          gAb + (it) * 16); CP16(d0 + 16,         gAb + (it) * 16 + 4); \
        CP16(d0 + 8192,   gAs + (it) * 16); CP16(d0 + 8192 + 16,  gAs + (it) * 16 + 4); \
        if (doB) { \
            CP16(d0 + 16384, gBb + (it) * 16); CP16(d0 + 16384 + 16, gBb + (it) * 16 + 4); \
        } \
        CP_COMMIT(); \
    } while (0)

    float acc[2][7][4];
#pragma unroll
    for (int mt = 0; mt < 2; mt++)
#pragma unroll
        for (int nt = 0; nt < 7; nt++)
#pragma unroll
            for (int c = 0; c < 4; c++) acc[mt][nt][c] = 0.f;

    const int nIter = 16;
    STAGE2(0, 0);
    STAGE2(1, 1);

    int buf = 0;
    for (int it = 0; it < nIter; it++) {
        if (it + 1 < nIter) { CP_WAIT1(); } else { CP_WAIT0(); }
        __syncthreads();
        if (it + 2 < nIter) {
            int nb = buf + 2; if (nb >= 3) nb -= 3;
            STAGE2(it + 2, nb);
        }
        const uint32_t* sA = sm + buf * 6144;
        const uint32_t* sB = sA + 4096;

        uint4 bb[7];
#pragma unroll
        for (int nt = 0; nt < 7; nt++) {
            const uint32_t* p = sB + (warp_n * 56 + nt * 8 + rw) * 16 + 4 * q;
            bb[nt] = *(const uint4*)p;
        }
#pragma unroll
        for (int mt = 0; mt < 2; mt++) {
            const uint32_t* p = sA + (warp_m * 32 + mt * 16 + rw) * 16 + 4 * q;
            uint4 alo = *(const uint4*)p;
            uint4 ahi = *(const uint4*)(p + 128);
            uint4 slo = *(const uint4*)(p + 2048);
            uint4 shi = *(const uint4*)(p + 2048 + 128);
#pragma unroll
            for (int nt = 0; nt < 7; nt++)
                mma_h(acc[mt][nt], alo.x, ahi.x, alo.y, ahi.y, bb[nt].x, bb[nt].y);
#pragma unroll
            for (int nt = 0; nt < 7; nt++)
                mma_h(acc[mt][nt], alo.z, ahi.z, alo.w, ahi.w, bb[nt].z, bb[nt].w);
#pragma unroll
            for (int nt = 0; nt < 7; nt++)
                mma_h(acc[mt][nt], slo.x, shi.x, slo.y, shi.y, bb[nt].x, bb[nt].y);
#pragma unroll
            for (int nt = 0; nt < 7; nt++)
                mma_h(acc[mt][nt], slo.z, shi.z, slo.w, shi.w, bb[nt].z, bb[nt].w);
        }
        buf++; if (buf >= 3) buf -= 3;
    }

    // ---- epilogue: bias -> smem tile ----
    __syncthreads();
    float* fs = (float*)sm;   // 128 x 113 fp32 = 57856 B <= 73728 B
#pragma unroll
    for (int mt = 0; mt < 2; mt++) {
#pragma unroll
        for (int nt = 0; nt < 7; nt++) {
            int r = warp_m * 32 + mt * 16 + rw;
            int c = warp_n * 56 + nt * 8 + q * 2;
            float b0 = bias[colBase + c], b1 = bias[colBase + c + 1];
            fs[r * 113 + c]           = acc[mt][nt][0] + b0;
            fs[r * 113 + c + 1]       = acc[mt][nt][1] + b1;
            fs[(r + 8) * 113 + c]     = acc[mt][nt][2] + b0;
            fs[(r + 8) * 113 + c + 1] = acc[mt][nt][3] + b1;
        }
    }
    __syncthreads();

    // ---- in-block spline: 1024 (row, d2) pairs, 4 per thread ----
    const int d2l = tid & 7;            // constant across iterations
    const int d2g = bx * 8 + d2l;       // global transformed dim 0..127
#pragma unroll
    for (int i = 0; i < 4; i++) {
        int p = tid + 256 * i;
        int r = p >> 3;                 // 0..127
        int n = rowBase + r;
        float raw[14];
#pragma unroll
        for (int j = 0; j < 14; j++) raw[j] = fs[r * 113 + d2l * 14 + j];
        float t = x[(size_t)n * 256 + xoff + d2g];
        float ld;
        float outv = spline_eval(raw, t, &ld);

        z[(size_t)n * 256 + zoff + d2g] = outv;

        if (zb != nullptr) {
            float nbv = __shfl_down_sync(0xffffffffu, outv, 1);
            if ((d2l & 1) == 0) {
                uint32_t bbv, ssv;
                split2h(outv, nbv, bbv, ssv);
                zb[n * 64 + gidx(d2g >> 1)] = bbv;
                zs[n * 64 + gidx(d2g >> 1)] = ssv;
            }
        }

        // reduce 8 lanes (same row) -> one partial
        float v = ld;
#pragma unroll
        for (int o = 4; o > 0; o >>= 1) v += __shfl_xor_sync(0xffffffffu, v, o);
        if (d2l == 0) ldpart[(size_t)n * 16 + bx] = v;
    }
#undef STAGE2
}

// ======================= final logdet reduce =======================
__global__ void __launch_bounds__(256) reduce_ld(
    const float* __restrict__ p1, const float* __restrict__ p2,
    float* __restrict__ logdet)
{
    int n = blockIdx.x * 256 + threadIdx.x;
    const float4* a = (const float4*)(p1 + (size_t)n * 16);
    const float4* b = (const float4*)(p2 + (size_t)n * 16);
    float s = 0.f;
#pragma unroll
    for (int i = 0; i < 4; i++) {
        float4 u = a[i];
        s += u.x + u.y + u.z + u.w;
    }
#pragma unroll
    for (int i = 0; i < 4; i++) {
        float4 u = b[i];
        s += u.x + u.y + u.z + u.w;
    }
    logdet[n] = s;
}

// ======================= host side =======================
extern "C" void kernel_launch(void* const* d_in, const int* in_sizes, int n_in,
                              void* d_out, int out_size)
{
    const float* x     = (const float*)d_in[0];
    const float* f0_w0 = (const float*)d_in[1];
    const float* f0_b0 = (const float*)d_in[2];
    const float* f0_w1 = (const float*)d_in[3];
    const float* f0_b1 = (const float*)d_in[4];
    const float* f1_w0 = (const float*)d_in[5];
    const float* f1_b0 = (const float*)d_in[6];
    const float* f1_w1 = (const float*)d_in[7];
    const float* f1_b1 = (const float*)d_in[8];

    const int N = in_sizes[0] / 256;              // 32768
    float* z      = (float*)d_out;
    float* logdet = z + (size_t)N * 256;

    uint32_t *xsb, *xss, *hb, *hs, *w0b, *w0s, *w1b, *w1s;
    float* ldp;
    cudaGetSymbolAddress((void**)&xsb, g_xs_big);
    cudaGetSymbolAddress((void**)&xss, g_xs_sml);
    cudaGetSymbolAddress((void**)&hb,  g_h_big);
    cudaGetSymbolAddress((void**)&hs,  g_h_sml);
    cudaGetSymbolAddress((void**)&w0b, g_w0b);
    cudaGetSymbolAddress((void**)&w0s, g_w0s);
    cudaGetSymbolAddress((void**)&w1b, g_w1b);
    cudaGetSymbolAddress((void**)&w1s, g_w1s);
    cudaGetSymbolAddress((void**)&ldp, g_ldp);
    float* ldp1 = ldp;
    float* ldp2 = ldp + (size_t)N * 16;

    cudaFuncSetAttribute((const void*)gemm1_h3,  cudaFuncAttributeMaxDynamicSharedMemorySize, GEMM_SMEM);
    cudaFuncSetAttribute((const void*)gemm2_fused, cudaFuncAttributeMaxDynamicSharedMemorySize, G2_SMEM);

    const dim3 g1(512 / 128, N / 128);    // (4, 256)
    const dim3 g2f(16, N / 128);          // (16, 256)
    const int nConvBlocks = N * 64 / 256; // 8192

    // ---- coupling 1 ----
    conv_all<<<960 + nConvBlocks, 256>>>(x, 0, f0_w0, f0_w1, f1_w0, f1_w1,
                                         w0b, w0s, w1b, w1s, xsb, xss);          // 1
    gemm1_h3<<<g1, 256, GEMM_SMEM>>>(xsb, xss, w0b, w0s, f0_b0, hb, hs, 512, 64); // 2
    gemm2_fused<<<g2f, 256, G2_SMEM>>>(hb, hs, w1b, f0_b1,
                                       x, 128, z, 128, xsb, xss, ldp1);          // 3 (spline fused; emits split z1)

    // ---- coupling 2 ----
    gemm1_h3<<<g1, 256, GEMM_SMEM>>>(xsb, xss, w0b + 512 * 64, w0s + 512 * 64,
                                     f1_b0, hb, hs, 512, 64);                    // 4
    gemm2_fused<<<g2f, 256, G2_SMEM>>>(hb, hs, w1b + 1792 * 256, f1_b1,
                                       x, 0, z, 0, nullptr, nullptr, ldp2);      // 5
    reduce_ld<<<N / 256, 256>>>(ldp1, ldp2, logdet);                             // 6
}